// round 3
// baseline (speedup 1.0000x reference)
#include <cuda_runtime.h>
#include <math.h>
#include <stdint.h>

// ---------------- static scratch (16B aligned for float4 paths) ----------------
__device__ __align__(16) float g_q    [40960u*224u];
__device__ __align__(16) float g_kv   [40960u*448u];
__device__ __align__(16) float g_attn [32*8*28*28];
__device__ __align__(16) float g_x1   [9175040];
__device__ __align__(16) float g_xn   [9175040];      // 286720 x 32
__device__ __align__(16) float g_xz   [36700160];     // 286720 x 128
__device__ __align__(16) float g_xc   [18350080];     // 286720 x 64
__device__ __align__(16) float g_xdbl [9748480];      // 286720 x 34
__device__ __align__(16) float g_dt   [18350080];
__device__ __align__(16) float g_Bm   [4587520];
__device__ __align__(16) float g_Cm   [4587520];
__device__ __align__(16) float g_y    [18350080];
__device__ __align__(16) float g_S    [2293760];      // 32*64*70*16
__device__ __align__(16) float g_sumdt[143360];       // 32*64*70
__device__ __align__(16) float g_H0   [2293760];
__device__ __align__(16) float g_xm2  [9175040];      // 286720 x 32
__device__ __align__(16) float g_x2   [9175040];
__device__ __align__(16) float g_x3   [9175040];
__device__ __align__(16) float g_xw   [11010048];     // 49152 x 224
__device__ __align__(16) float g_qkvw [33030144];     // 49152 x 672
__device__ __align__(16) float g_obuf [11010048];
__device__ __align__(16) float g_oproj[11010048];

__device__ __forceinline__ float siluf(float v){ return v / (1.f + __expf(-v)); }

// ---------------- big SGEMM: 128x128 tile, 8x8 micro, BK=8, double-buffered ----
// Requires M % 128 == 0, K % 8 == 0, lda % 4 == 0, A 16B-aligned. N predicated.
__global__ __launch_bounds__(256) void sgemm128(
    const float* __restrict__ A, const float* __restrict__ B,
    float* __restrict__ C, const float* __restrict__ bias,
    int N, int K, int lda, int ldb, int ldc)
{
    __shared__ float As[2][8][128];
    __shared__ float Bs[2][8][128];
    const int bm = blockIdx.y * 128;
    const int bn = blockIdx.x * 128;
    const int tid = threadIdx.x;
    const int tr = tid >> 4, tc = tid & 15;
    // A loader: 128 rows x 8 k, float4 per thread
    const int am = tid >> 1;
    const int ak = (tid & 1) * 4;
    // B loader: 8 k-rows x 128 cols, 4 scalars per thread (predicated on N)
    const int bk  = tid >> 5;
    const int bn0 = (tid & 31) * 4;

    const float* Aptr = A + (size_t)(bm + am) * lda + ak;
    const float* Bptr = B + (size_t)bk * ldb + bn + bn0;

    float acc[8][8];
    #pragma unroll
    for (int i = 0; i < 8; i++)
        #pragma unroll
        for (int j = 0; j < 8; j++) acc[i][j] = 0.f;

    // prefetch tile 0
    float4 ra = *(const float4*)Aptr;
    float rb[4];
    #pragma unroll
    for (int i = 0; i < 4; i++) {
        int n = bn + bn0 + i;
        rb[i] = (n < N) ? Bptr[i] : 0.f;
    }
    int buf = 0;
    As[0][ak+0][am] = ra.x; As[0][ak+1][am] = ra.y;
    As[0][ak+2][am] = ra.z; As[0][ak+3][am] = ra.w;
    #pragma unroll
    for (int i = 0; i < 4; i++) Bs[0][bk][bn0+i] = rb[i];
    __syncthreads();

    for (int k0 = 0; k0 < K; k0 += 8) {
        const bool more = (k0 + 8) < K;
        float4 ra2; float rb2[4];
        if (more) {
            ra2 = *(const float4*)(Aptr + k0 + 8);
            const float* bp = Bptr + (size_t)(k0 + 8) * ldb;
            #pragma unroll
            for (int i = 0; i < 4; i++) {
                int n = bn + bn0 + i;
                rb2[i] = (n < N) ? bp[i] : 0.f;
            }
        }
        #pragma unroll
        for (int kk = 0; kk < 8; kk++) {
            float a[8], b[8];
            *(float4*)&a[0] = *(const float4*)&As[buf][kk][tr*8];
            *(float4*)&a[4] = *(const float4*)&As[buf][kk][tr*8+4];
            *(float4*)&b[0] = *(const float4*)&Bs[buf][kk][tc*8];
            *(float4*)&b[4] = *(const float4*)&Bs[buf][kk][tc*8+4];
            #pragma unroll
            for (int i = 0; i < 8; i++)
                #pragma unroll
                for (int j = 0; j < 8; j++) acc[i][j] += a[i]*b[j];
        }
        if (more) {
            buf ^= 1;
            As[buf][ak+0][am] = ra2.x; As[buf][ak+1][am] = ra2.y;
            As[buf][ak+2][am] = ra2.z; As[buf][ak+3][am] = ra2.w;
            #pragma unroll
            for (int i = 0; i < 4; i++) Bs[buf][bk][bn0+i] = rb2[i];
            __syncthreads();
        }
    }
    #pragma unroll
    for (int i = 0; i < 8; i++) {
        size_t m = bm + tr*8 + i;
        #pragma unroll
        for (int j = 0; j < 8; j++) {
            int n = bn + tc*8 + j;
            if (n < N) {
                float v = acc[i][j];
                if (bias) v += bias[n];
                C[m * ldc + n] = v;
            }
        }
    }
}

// ---------------- small-N SGEMM (kept for x_proj, N=34) ----------------
__global__ void sgemm_k(const float* __restrict__ A, const float* __restrict__ B,
                        float* __restrict__ C, const float* __restrict__ bias,
                        int N, int K, int lda, int ldb, int ldc) {
    __shared__ float As[16][128];
    __shared__ float Bs[16][64];
    const int bm = blockIdx.y * 128, bn = blockIdx.x * 64;
    const int tid = threadIdx.x;
    const int tr = tid >> 4, tc = tid & 15;
    float acc[8][4];
    #pragma unroll
    for (int i = 0; i < 8; i++)
        #pragma unroll
        for (int j = 0; j < 4; j++) acc[i][j] = 0.f;

    for (int k0 = 0; k0 < K; k0 += 16) {
        #pragma unroll
        for (int i = 0; i < 2; i++) {
            int idx = tid + i * 256;
            int r = idx >> 2, c4 = (idx & 3) * 4;
            float4 v = *(const float4*)(A + (size_t)(bm + r) * lda + k0 + c4);
            As[c4+0][r]=v.x; As[c4+1][r]=v.y; As[c4+2][r]=v.z; As[c4+3][r]=v.w;
        }
        {
            int r = tid >> 4, c0 = (tid & 15) * 4;
            #pragma unroll
            for (int i = 0; i < 4; i++) {
                int n = bn + c0 + i;
                Bs[r][c0+i] = (n < N) ? B[(size_t)(k0 + r) * ldb + n] : 0.f;
            }
        }
        __syncthreads();
        #pragma unroll
        for (int kk = 0; kk < 16; kk++) {
            float4 a0 = *(const float4*)&As[kk][tr*8];
            float4 a1 = *(const float4*)&As[kk][tr*8+4];
            float4 b0 = *(const float4*)&Bs[kk][tc*4];
            float a[8] = {a0.x,a0.y,a0.z,a0.w,a1.x,a1.y,a1.z,a1.w};
            float b[4] = {b0.x,b0.y,b0.z,b0.w};
            #pragma unroll
            for (int i = 0; i < 8; i++)
                #pragma unroll
                for (int j = 0; j < 4; j++) acc[i][j] += a[i]*b[j];
        }
        __syncthreads();
    }
    #pragma unroll
    for (int i = 0; i < 8; i++) {
        int m = bm + tr*8 + i;
        #pragma unroll
        for (int j = 0; j < 4; j++) {
            int n = bn + tc*4 + j;
            if (n < N) {
                float v = acc[i][j];
                if (bias) v += bias[n];
                C[(size_t)m * ldc + n] = v;
            }
        }
    }
}

// ---------------- stage 1: channel attention ----------------
__global__ void k_gram(const float* __restrict__ q, const float* __restrict__ kv,
                       float* __restrict__ attn) {
    int b = blockIdx.x, h = blockIdx.y;
    __shared__ float kt[32][28], qt[32][28];
    __shared__ float G[840];
    int tid = threadIdx.x;   // 256
    float acc[4] = {0.f,0.f,0.f,0.f};
    for (int nt = 0; nt < 40; nt++) {
        for (int idx = tid; idx < 896; idx += 256) {
            int n = idx / 28, i = idx % 28;
            size_t row = (size_t)b*1280 + nt*32 + n;
            kt[n][i] = kv[row*448 + h*28 + i];
            qt[n][i] = q [row*224 + h*28 + i];
        }
        __syncthreads();
        #pragma unroll
        for (int s = 0; s < 4; s++) {
            int w = tid + 256*s;
            if (w < 784) {
                int i = w/28, j = w%28; float a = acc[s];
                #pragma unroll
                for (int n = 0; n < 32; n++) a += kt[n][i]*qt[n][j];
                acc[s] = a;
            } else if (w < 812) {
                int i = w - 784; float a = acc[s];
                #pragma unroll
                for (int n = 0; n < 32; n++) a += kt[n][i]*kt[n][i];
                acc[s] = a;
            } else if (w < 840) {
                int j = w - 812; float a = acc[s];
                #pragma unroll
                for (int n = 0; n < 32; n++) a += qt[n][j]*qt[n][j];
                acc[s] = a;
            }
        }
        __syncthreads();
    }
    #pragma unroll
    for (int s = 0; s < 4; s++) { int w = tid + 256*s; if (w < 840) G[w] = acc[s]; }
    __syncthreads();
    if (tid < 28) {
        int i = tid;
        float nk = fmaxf(sqrtf(G[784+i]), 1e-12f);
        float lg[28], m = -1e30f;
        #pragma unroll
        for (int j = 0; j < 28; j++) {
            float nq = fmaxf(sqrtf(G[812+j]), 1e-12f);
            lg[j] = G[i*28+j] / (nk*nq) * 0.18898223650461363f;
            m = fmaxf(m, lg[j]);
        }
        float sum = 0.f;
        #pragma unroll
        for (int j = 0; j < 28; j++) { lg[j] = __expf(lg[j]-m); sum += lg[j]; }
        float inv = 1.f/sum;
        #pragma unroll
        for (int j = 0; j < 28; j++)
            attn[(((size_t)b*8 + h)*28 + i)*28 + j] = lg[j]*inv;
    }
}

// x1 = attn-applied + residual; 4 rows per barrier interval
__global__ void k_apply(const float* __restrict__ x, const float* __restrict__ kv,
                        const float* __restrict__ attn, float* __restrict__ x1) {
    int chunk = blockIdx.x, b = blockIdx.y;
    __shared__ float att[6272];
    __shared__ float vr[4][224];
    int tid = threadIdx.x;   // 224
    for (int idx = tid; idx < 6272; idx += 224) att[idx] = attn[(size_t)b*6272 + idx];
    int h = tid / 28, i = tid % 28;
    for (int nn = 0; nn < 64; nn += 4) {
        size_t row0 = (size_t)b*1280 + chunk*64 + nn;
        __syncthreads();
        for (int idx = tid; idx < 896; idx += 224) {
            int rr = idx / 224, cc = idx % 224;
            vr[rr][cc] = kv[(row0 + rr)*448 + 224 + cc];
        }
        __syncthreads();
        #pragma unroll
        for (int rr = 0; rr < 4; rr++) {
            float a = 0.f;
            #pragma unroll
            for (int j = 0; j < 28; j++) a += att[(h*28+i)*28 + j] * vr[rr][h*28 + j];
            size_t o = (row0 + rr)*224 + tid;
            x1[o] = x[o] + a;
        }
    }
}

// ---------------- transpose + LN into (b, L=8960, 32) ----------------
__global__ void k_ln1(const float* __restrict__ x1, const float* __restrict__ g,
                      const float* __restrict__ be, float* __restrict__ xn) {
    int ww = blockIdx.x, b = blockIdx.y;
    __shared__ float s[32*225];
    int tid = threadIdx.x;   // 256
    for (int idx = tid; idx < 32*224; idx += 256) {
        int m = idx / 224, cc = idx % 224;
        s[m*225 + cc] = x1[((size_t)b*1280 + m*40 + ww)*224 + cc];
    }
    __syncthreads();
    for (int cc = tid; cc < 224; cc += 256) {
        float mean = 0.f;
        #pragma unroll
        for (int m = 0; m < 32; m++) mean += s[m*225+cc];
        mean *= (1.f/32.f);
        float var = 0.f;
        #pragma unroll
        for (int m = 0; m < 32; m++) { float d = s[m*225+cc]-mean; var += d*d; }
        var *= (1.f/32.f);
        float inv = rsqrtf(var + 1e-5f);
        size_t ob = ((size_t)b*8960 + ww*224 + cc)*32;
        #pragma unroll
        for (int m = 0; m < 32; m++)
            xn[ob + m] = (s[m*225+cc]-mean)*inv*g[m] + be[m];
    }
}

// ---------------- mamba pieces ----------------
__global__ void k_conv1d(const float* __restrict__ xz, const float* __restrict__ cw,
                         const float* __restrict__ cb, float* __restrict__ xc) {
    size_t id = (size_t)blockIdx.x*256 + threadIdx.x;
    size_t row = id >> 6; int d = (int)(id & 63);
    size_t b = row / 8960; int l = (int)(row % 8960);
    float acc = cb[d];
    #pragma unroll
    for (int t = 0; t < 4; t++) {
        int ls = l - 3 + t;
        if (ls >= 0) acc += xz[((size_t)b*8960 + ls)*128 + d] * cw[d*4 + t];
    }
    xc[row*64 + d] = siluf(acc);
}

__global__ void k_dtbc(const float* __restrict__ xdbl, const float* __restrict__ dtW,
                       const float* __restrict__ dtb, float* __restrict__ dt,
                       float* __restrict__ Bm, float* __restrict__ Cm) {
    size_t id = (size_t)blockIdx.x*256 + threadIdx.x;
    size_t row = id / 96; int j = (int)(id % 96);
    const float* xd = xdbl + row*34;
    if (j < 64) {
        float v = xd[0]*dtW[j] + xd[1]*dtW[64+j] + dtb[j];
        dt[row*64 + j] = (v > 20.f) ? v : log1pf(__expf(v));
    } else if (j < 80) {
        Bm[row*16 + (j-64)] = xd[2 + (j-64)];
    } else {
        Cm[row*16 + (j-80)] = xd[18 + (j-80)];
    }
}

__global__ void k_scan1(const float* __restrict__ dt, const float* __restrict__ xc,
                        const float* __restrict__ Bm, const float* __restrict__ Alog,
                        float* __restrict__ S, float* __restrict__ sumdt) {
    int gw = (blockIdx.x*256 + threadIdx.x) >> 5;
    int lane = threadIdx.x & 31;
    int b = gw / 2240; int rem = gw % 2240;
    int chunk = rem >> 5; int dp = rem & 31;
    int d = dp*2 + (lane >> 4); int n = lane & 15;
    float Av = -__expf(Alog[d*16 + n]);
    float h = 0.f, sdt = 0.f;
    size_t base = (size_t)b*8960 + chunk*128;
    for (int l = 0; l < 128; l++) {
        size_t row = base + l;
        float dtv = dt[row*64 + d];
        float u   = xc[row*64 + d];
        float Bn  = Bm[row*16 + n];
        h = __expf(Av*dtv)*h + dtv*u*Bn;
        sdt += dtv;
    }
    size_t idx = (size_t)(b*64 + d)*70 + chunk;
    S[idx*16 + n] = h;
    if (n == 0) sumdt[idx] = sdt;
}

__global__ void k_scan2(const float* __restrict__ S, const float* __restrict__ sumdt,
                        const float* __restrict__ Alog, float* __restrict__ H0) {
    int t = blockIdx.x*256 + threadIdx.x;
    int b = t >> 10; int d = (t >> 4) & 63; int n = t & 15;
    float Av = -__expf(Alog[d*16 + n]);
    float carry = 0.f;
    size_t base = (size_t)(b*64 + d)*70;
    for (int ch = 0; ch < 70; ch++) {
        size_t idx = base + ch;
        H0[idx*16 + n] = carry;
        carry = carry*__expf(Av*sumdt[idx]) + S[idx*16 + n];
    }
}

__global__ void k_scan3(const float* __restrict__ dt, const float* __restrict__ xc,
                        const float* __restrict__ Bm, const float* __restrict__ Cm,
                        const float* __restrict__ Alog, const float* __restrict__ H0,
                        float* __restrict__ y) {
    int gw = (blockIdx.x*256 + threadIdx.x) >> 5;
    int lane = threadIdx.x & 31;
    int b = gw / 2240; int rem = gw % 2240;
    int chunk = rem >> 5; int dp = rem & 31;
    int d = dp*2 + (lane >> 4); int n = lane & 15;
    float Av = -__expf(Alog[d*16 + n]);
    size_t idx = (size_t)(b*64 + d)*70 + chunk;
    float h = H0[idx*16 + n];
    size_t base = (size_t)b*8960 + chunk*128;
    for (int l = 0; l < 128; l++) {
        size_t row = base + l;
        float dtv = dt[row*64 + d];
        float u   = xc[row*64 + d];
        float Bn  = Bm[row*16 + n];
        h = __expf(Av*dtv)*h + dtv*u*Bn;
        float yv = h * Cm[row*16 + n];
        yv += __shfl_xor_sync(0xffffffffu, yv, 8);
        yv += __shfl_xor_sync(0xffffffffu, yv, 4);
        yv += __shfl_xor_sync(0xffffffffu, yv, 2);
        yv += __shfl_xor_sync(0xffffffffu, yv, 1);
        if (n == 0) y[row*64 + d] = yv;
    }
}

__global__ void k_final(const float* __restrict__ y, const float* __restrict__ xc,
                        const float* __restrict__ xz, const float* __restrict__ xn,
                        const float* __restrict__ Dp, const float* __restrict__ opW,
                        const float* __restrict__ skipp, const float* __restrict__ g,
                        const float* __restrict__ be, const float* __restrict__ projW,
                        const float* __restrict__ projb, float* __restrict__ xm2) {
    __shared__ float sop[2048], spj[1024];
    int tid = threadIdx.x;   // 256
    for (int i = tid; i < 2048; i += 256) sop[i] = opW[i];
    for (int i = tid; i < 1024; i += 256) spj[i] = projW[i];
    __syncthreads();
    int warp = tid >> 5, lane = tid & 31;
    size_t r = (size_t)blockIdx.x*8 + warp;
    float skip = skipp[0];
    float y0 = y[r*64 + lane],      y1 = y[r*64 + 32 + lane];
    float c0 = xc[r*64 + lane],     c1 = xc[r*64 + 32 + lane];
    float z0 = xz[r*128 + 64 + lane], z1 = xz[r*128 + 96 + lane];
    float yy0 = (y0 + c0*Dp[lane])    * siluf(z0);
    float yy1 = (y1 + c1*Dp[32+lane]) * siluf(z1);
    float acc = 0.f;
    #pragma unroll
    for (int d = 0; d < 32; d++) acc += __shfl_sync(0xffffffffu, yy0, d) * sop[d*32 + lane];
    #pragma unroll
    for (int d = 0; d < 32; d++) acc += __shfl_sync(0xffffffffu, yy1, d) * sop[(d+32)*32 + lane];
    float xm = acc + skip * xn[r*32 + lane];
    float mean = xm;
    #pragma unroll
    for (int o = 16; o; o >>= 1) mean += __shfl_xor_sync(0xffffffffu, mean, o);
    mean *= (1.f/32.f);
    float dv = xm - mean, var = dv*dv;
    #pragma unroll
    for (int o = 16; o; o >>= 1) var += __shfl_xor_sync(0xffffffffu, var, o);
    var *= (1.f/32.f);
    float v = dv * rsqrtf(var + 1e-5f) * g[lane] + be[lane];
    float acc2 = projb[lane];
    #pragma unroll
    for (int mm = 0; mm < 32; mm++) acc2 += __shfl_sync(0xffffffffu, v, mm) * spj[mm*32 + lane];
    xm2[r*32 + lane] = acc2;
}

__global__ void k_addback(const float* __restrict__ x1, const float* __restrict__ xm2,
                          float* __restrict__ x2) {
    int ww = blockIdx.x, b = blockIdx.y;
    __shared__ float s[224*33];
    int tid = threadIdx.x;   // 256
    for (int idx = tid; idx < 224*32; idx += 256) {
        int cc = idx >> 5, m = idx & 31;
        s[cc*33 + m] = xm2[((size_t)b*8960 + ww*224 + cc)*32 + m];
    }
    __syncthreads();
    for (int idx = tid; idx < 32*224; idx += 256) {
        int m = idx / 224, cc = idx % 224;
        size_t o = ((size_t)b*1280 + m*40 + ww)*224 + cc;
        x2[o] = x1[o] + s[cc*33 + m];
    }
}

// ---------------- conv3d 5x5x5, pad 2 ----------------
__global__ void k_conv3d(const float* __restrict__ x2, const float* __restrict__ cw,
                         const float* __restrict__ cb, float* __restrict__ x3) {
    int y = blockIdx.x, b = blockIdx.y;
    int xx = threadIdx.x;   // 224
    __shared__ float ws[125];
    if (xx < 125) ws[xx] = cw[xx];
    __syncthreads();
    float acc[32];
    #pragma unroll
    for (int d = 0; d < 32; d++) acc[d] = 0.f;
    for (int ky = 0; ky < 5; ky++) {
        int yy = y + ky - 2;
        if (yy < 0 || yy >= 40) continue;
        for (int kx = 0; kx < 5; kx++) {
            int x2i = xx + kx - 2;
            if (x2i < 0 || x2i >= 224) continue;
            float v[36];
            v[0]=v[1]=v[34]=v[35]=0.f;
            #pragma unroll
            for (int i = 2; i < 34; i++)
                v[i] = x2[(((size_t)b*32 + (i-2))*40 + yy)*224 + x2i];
            #pragma unroll
            for (int kz = 0; kz < 5; kz++) {
                float wv = ws[(kz*5 + ky)*5 + kx];
                #pragma unroll
                for (int d = 0; d < 32; d++) acc[d] += v[d+kz]*wv;
            }
        }
    }
    float bias = cb[0];
    #pragma unroll
    for (int d = 0; d < 32; d++)
        x3[(((size_t)b*32 + d)*40 + y)*224 + xx] = acc[d] + bias;
}

// ---------------- DWT + reflect-pad + window pack ----------------
__global__ void k_dwt(const float* __restrict__ x3, float* __restrict__ xw) {
    size_t id = (size_t)blockIdx.x*256 + threadIdx.x;   // 11010048
    int c = (int)(id % 224); size_t r = id / 224;
    int sub = (int)(r / 12288); int rw = (int)(r % 12288);
    int win = rw >> 6, tok = rw & 63;
    int bb = win / 6, w6 = win % 6;
    int wi = w6 / 3, wj = w6 % 3;
    int ti = tok >> 3, tj = tok & 7;
    int i2 = wi*8 + ti;
    int j2 = wj*8 + tj;
    int j = (j2 < 20) ? j2 : 38 - j2;   // reflect pad
    size_t base = (((size_t)bb*32 + 2*i2)*40 + 2*j)*224 + c;
    float a  = x3[base],        bv = x3[base + 224];
    float c2 = x3[base + 8960], d2 = x3[base + 9184];
    float val;
    if      (sub == 0) val = a + bv + c2 + d2;
    else if (sub == 1) val = a + bv - c2 - d2;
    else if (sub == 2) val = a - bv + c2 - d2;
    else               val = a - bv - c2 + d2;
    xw[id] = 0.5f * val;
}

// ---------------- window attention ----------------
__global__ void k_wattn(const float* __restrict__ qkvw, const float* __restrict__ pe,
                        float* __restrict__ obuf) {
    int win = blockIdx.x, head = blockIdx.y;
    __shared__ float qs[64*28], ks[64*28], vs[64*28];
    __shared__ float lgs[64*65];
    int tid = threadIdx.x;   // 64
    size_t wbase = (size_t)win * 64;
    for (int idx = tid; idx < 1792; idx += 64) {
        int tok = idx / 28, dd = idx % 28;
        size_t rb = (wbase + tok)*672 + head*28 + dd;
        qs[idx] = qkvw[rb] * 0.18898223650461363f;
        ks[idx] = qkvw[rb + 224];
        vs[idx] = qkvw[rb + 448];
    }
    __syncthreads();
    int i = tid;
    float qr[28];
    #pragma unroll
    for (int dd = 0; dd < 28; dd++) qr[dd] = qs[i*28 + dd];
    const float* per = pe + ((size_t)head*64 + i)*64;
    float m = -1e30f;
    for (int j = 0; j < 64; j++) {
        float dot = 0.f;
        #pragma unroll
        for (int dd = 0; dd < 28; dd++) dot += qr[dd]*ks[j*28 + dd];
        float l = dot + per[j];
        lgs[i*65 + j] = l;
        m = fmaxf(m, l);
    }
    float sum = 0.f;
    for (int j = 0; j < 64; j++) {
        float e = __expf(lgs[i*65 + j] - m);
        lgs[i*65 + j] = e;
        sum += e;
    }
    float inv = 1.f / sum;
    float acc[28];
    #pragma unroll
    for (int dd = 0; dd < 28; dd++) acc[dd] = 0.f;
    for (int j = 0; j < 64; j++) {
        float a = lgs[i*65 + j] * inv;
        #pragma unroll
        for (int dd = 0; dd < 28; dd++) acc[dd] += a*vs[j*28 + dd];
    }
    size_t ob = (wbase + i)*224 + head*28;
    #pragma unroll
    for (int dd = 0; dd < 28; dd++) obuf[ob + dd] = acc[dd];
}

// ---------------- IWT + crop + final layout ----------------
__global__ void k_iwt(const float* __restrict__ oproj, float* __restrict__ out) {
    size_t id = (size_t)blockIdx.x*256 + threadIdx.x;   // 2293760
    int c = (int)(id % 224); size_t r = id / 224;
    int j = (int)(r % 20); r /= 20;
    int i = (int)(r % 16); int bb = (int)(r / 16);
    int wi = i >> 3, ti = i & 7, wj = j >> 3, tj = j & 7;
    size_t row0 = ((size_t)(bb*6 + wi*3 + wj))*64 + ti*8 + tj;
    float A  = oproj[row0*224 + c];
    float Hh = oproj[(row0 + 12288)*224 + c];
    float V  = oproj[(row0 + 24576)*224 + c];
    float D  = oproj[(row0 + 36864)*224 + c];
    size_t oo = (((size_t)bb*32 + 2*i)*40 + 2*j)*224 + c;
    out[oo]          = 0.5f*(A + Hh + V + D);
    out[oo + 224]    = 0.5f*(A + Hh - V - D);
    out[oo + 8960]   = 0.5f*(A - Hh + V - D);
    out[oo + 9184]   = 0.5f*(A - Hh - V + D);
}

// ---------------- launcher ----------------
extern "C" void kernel_launch(void* const* d_in, const int* in_sizes, int n_in,
                              void* d_out, int out_size) {
    const float* x       = (const float*)d_in[0];
    const float* Wq      = (const float*)d_in[1];
    const float* Wkv     = (const float*)d_in[2];
    const float* ln_g    = (const float*)d_in[3];
    const float* ln_b    = (const float*)d_in[4];
    const float* in_proj = (const float*)d_in[5];
    const float* conv1dW = (const float*)d_in[6];
    const float* conv1db = (const float*)d_in[7];
    const float* x_projW = (const float*)d_in[8];
    const float* dt_projW= (const float*)d_in[9];
    const float* dt_projb= (const float*)d_in[10];
    const float* A_log   = (const float*)d_in[11];
    const float* Dp      = (const float*)d_in[12];
    const float* out_projW=(const float*)d_in[13];
    const float* skip    = (const float*)d_in[14];
    const float* projW   = (const float*)d_in[15];
    const float* projb   = (const float*)d_in[16];
    const float* conv3dW = (const float*)d_in[17];
    const float* conv3db = (const float*)d_in[18];
    const float* Wq1     = (const float*)d_in[19];
    const float* Wkv1    = (const float*)d_in[20];
    const float* pos_emb = (const float*)d_in[21];
    const float* Wo[4]   = {(const float*)d_in[22],(const float*)d_in[24],
                            (const float*)d_in[26],(const float*)d_in[28]};
    const float* bo[4]   = {(const float*)d_in[23],(const float*)d_in[25],
                            (const float*)d_in[27],(const float*)d_in[29]};
    float* out = (float*)d_out;

    float *p_q, *p_kv, *p_attn, *p_x1, *p_xn, *p_xz, *p_xc, *p_xdbl, *p_dt,
          *p_Bm, *p_Cm, *p_y, *p_S, *p_sd, *p_H0, *p_xm2, *p_x2, *p_x3,
          *p_xw, *p_qkvw, *p_obuf, *p_oproj;
    cudaGetSymbolAddress((void**)&p_q,    g_q);
    cudaGetSymbolAddress((void**)&p_kv,   g_kv);
    cudaGetSymbolAddress((void**)&p_attn, g_attn);
    cudaGetSymbolAddress((void**)&p_x1,   g_x1);
    cudaGetSymbolAddress((void**)&p_xn,   g_xn);
    cudaGetSymbolAddress((void**)&p_xz,   g_xz);
    cudaGetSymbolAddress((void**)&p_xc,   g_xc);
    cudaGetSymbolAddress((void**)&p_xdbl, g_xdbl);
    cudaGetSymbolAddress((void**)&p_dt,   g_dt);
    cudaGetSymbolAddress((void**)&p_Bm,   g_Bm);
    cudaGetSymbolAddress((void**)&p_Cm,   g_Cm);
    cudaGetSymbolAddress((void**)&p_y,    g_y);
    cudaGetSymbolAddress((void**)&p_S,    g_S);
    cudaGetSymbolAddress((void**)&p_sd,   g_sumdt);
    cudaGetSymbolAddress((void**)&p_H0,   g_H0);
    cudaGetSymbolAddress((void**)&p_xm2,  g_xm2);
    cudaGetSymbolAddress((void**)&p_x2,   g_x2);
    cudaGetSymbolAddress((void**)&p_x3,   g_x3);
    cudaGetSymbolAddress((void**)&p_xw,   g_xw);
    cudaGetSymbolAddress((void**)&p_qkvw, g_qkvw);
    cudaGetSymbolAddress((void**)&p_obuf, g_obuf);
    cudaGetSymbolAddress((void**)&p_oproj,g_oproj);

    // stage 1: q/kv GEMMs, gram+softmax, apply
    sgemm128<<<dim3(2, 320), 256>>>(x, Wq,  p_q,  nullptr, 224, 224, 224, 224, 224);
    sgemm128<<<dim3(4, 320), 256>>>(x, Wkv, p_kv, nullptr, 448, 224, 224, 448, 448);
    k_gram <<<dim3(32, 8), 256>>>(p_q, p_kv, p_attn);
    k_apply<<<dim3(20, 32), 224>>>(x, p_kv, p_attn, p_x1);

    // stage 2: mamba
    k_ln1<<<dim3(40, 32), 256>>>(p_x1, ln_g, ln_b, p_xn);
    sgemm128<<<dim3(1, 2240), 256>>>(p_xn, in_proj, p_xz, nullptr, 128, 32, 32, 128, 128);
    k_conv1d<<<71680, 256>>>(p_xz, conv1dW, conv1db, p_xc);
    sgemm_k<<<dim3(1, 2240), 256>>>(p_xc, x_projW, p_xdbl, nullptr, 34, 64, 64, 34, 34);
    k_dtbc<<<107520, 256>>>(p_xdbl, dt_projW, dt_projb, p_dt, p_Bm, p_Cm);
    k_scan1<<<8960, 256>>>(p_dt, p_xc, p_Bm, A_log, p_S, p_sd);
    k_scan2<<<128, 256>>>(p_S, p_sd, A_log, p_H0);
    k_scan3<<<8960, 256>>>(p_dt, p_xc, p_Bm, p_Cm, A_log, p_H0, p_y);
    k_final<<<35840, 256>>>(p_y, p_xc, p_xz, p_xn, Dp, out_projW, skip,
                            ln_g, ln_b, projW, projb, p_xm2);
    k_addback<<<dim3(40, 32), 256>>>(p_x1, p_xm2, p_x2);

    // stage 3: conv3d
    k_conv3d<<<dim3(40, 32), 224>>>(p_x2, conv3dW, conv3db, p_x3);

    // stage 4: DWT + window attention
    k_dwt<<<43008, 256>>>(p_x3, p_xw);
    sgemm128<<<dim3(2, 384), 256>>>(p_xw, Wq1,  p_qkvw,       nullptr, 224, 224, 224, 224, 672);
    sgemm128<<<dim3(4, 384), 256>>>(p_xw, Wkv1, p_qkvw + 224, nullptr, 448, 224, 224, 448, 672);
    k_wattn<<<dim3(768, 8), 64>>>(p_qkvw, pos_emb, p_obuf);
    for (int s = 0; s < 4; s++) {
        sgemm128<<<dim3(2, 96), 256>>>(p_obuf + (size_t)s*12288*224, Wo[s],
                                       p_oproj + (size_t)s*12288*224, bo[s],
                                       224, 224, 224, 224, 224);
    }

    // stage 5: IWT + output
    k_iwt<<<8960, 256>>>(p_oproj, out);
}

// round 4
// speedup vs baseline: 1.3258x; 1.3258x over previous
#include <cuda_runtime.h>
#include <math.h>
#include <stdint.h>

// ---------------- static scratch (16B aligned for float4 paths) ----------------
__device__ __align__(16) float g_q    [40960u*224u];
__device__ __align__(16) float g_kv   [40960u*448u];
__device__ __align__(16) float g_attn [32*8*28*28];
__device__ __align__(16) float g_x1   [9175040];
__device__ __align__(16) float g_xn   [9175040];      // 286720 x 32
__device__ __align__(16) float g_xz   [36700160];     // 286720 x 128
__device__ __align__(16) float g_xc   [18350080];     // 286720 x 64
__device__ __align__(16) float g_xdbl [9748480];      // 286720 x 34
__device__ __align__(16) float g_dt   [18350080];
__device__ __align__(16) float g_Bm   [4587520];
__device__ __align__(16) float g_Cm   [4587520];
__device__ __align__(16) float g_y    [18350080];
__device__ __align__(16) float g_S    [2293760];      // 32*64*70*16
__device__ __align__(16) float g_sumdt[143360];       // 32*64*70
__device__ __align__(16) float g_H0   [2293760];
__device__ __align__(16) float g_xm2  [9175040];      // 286720 x 32
__device__ __align__(16) float g_x2   [9175040];
__device__ __align__(16) float g_x3   [9175040];
__device__ __align__(16) float g_xw   [11010048];     // 49152 x 224
__device__ __align__(16) float g_qkvw [33030144];     // 49152 x 672
__device__ __align__(16) float g_obuf [11010048];
__device__ __align__(16) float g_oproj[11010048];

__device__ __forceinline__ float siluf(float v){ return v / (1.f + __expf(-v)); }

// ---------------- big SGEMM: 128x128 tile, 8x8 micro, BK=8, double-buffered ----
// Requires M % 128 == 0, K % 8 == 0, lda % 4 == 0, A 16B-aligned. N predicated.
__global__ __launch_bounds__(256) void sgemm128(
    const float* __restrict__ A, const float* __restrict__ B,
    float* __restrict__ C, const float* __restrict__ bias,
    int N, int K, int lda, int ldb, int ldc)
{
    __shared__ float As[2][8][128];
    __shared__ float Bs[2][8][128];
    const int bm = blockIdx.y * 128;
    const int bn = blockIdx.x * 128;
    const int tid = threadIdx.x;
    const int tr = tid >> 4, tc = tid & 15;
    // A loader: 128 rows x 8 k, float4 per thread
    const int am = tid >> 1;
    const int ak = (tid & 1) * 4;
    // B loader: 8 k-rows x 128 cols, 4 scalars per thread (predicated on N)
    const int bk  = tid >> 5;
    const int bn0 = (tid & 31) * 4;

    const float* Aptr = A + (size_t)(bm + am) * lda + ak;
    const float* Bptr = B + (size_t)bk * ldb + bn + bn0;

    float acc[8][8];
    #pragma unroll
    for (int i = 0; i < 8; i++)
        #pragma unroll
        for (int j = 0; j < 8; j++) acc[i][j] = 0.f;

    // prefetch tile 0
    float4 ra = *(const float4*)Aptr;
    float rb[4];
    #pragma unroll
    for (int i = 0; i < 4; i++) {
        int n = bn + bn0 + i;
        rb[i] = (n < N) ? Bptr[i] : 0.f;
    }
    int buf = 0;
    As[0][ak+0][am] = ra.x; As[0][ak+1][am] = ra.y;
    As[0][ak+2][am] = ra.z; As[0][ak+3][am] = ra.w;
    #pragma unroll
    for (int i = 0; i < 4; i++) Bs[0][bk][bn0+i] = rb[i];
    __syncthreads();

    for (int k0 = 0; k0 < K; k0 += 8) {
        const bool more = (k0 + 8) < K;
        float4 ra2; float rb2[4];
        if (more) {
            ra2 = *(const float4*)(Aptr + k0 + 8);
            const float* bp = Bptr + (size_t)(k0 + 8) * ldb;
            #pragma unroll
            for (int i = 0; i < 4; i++) {
                int n = bn + bn0 + i;
                rb2[i] = (n < N) ? bp[i] : 0.f;
            }
        }
        #pragma unroll
        for (int kk = 0; kk < 8; kk++) {
            float a[8], b[8];
            *(float4*)&a[0] = *(const float4*)&As[buf][kk][tr*8];
            *(float4*)&a[4] = *(const float4*)&As[buf][kk][tr*8+4];
            *(float4*)&b[0] = *(const float4*)&Bs[buf][kk][tc*8];
            *(float4*)&b[4] = *(const float4*)&Bs[buf][kk][tc*8+4];
            #pragma unroll
            for (int i = 0; i < 8; i++)
                #pragma unroll
                for (int j = 0; j < 8; j++) acc[i][j] += a[i]*b[j];
        }
        if (more) {
            buf ^= 1;
            As[buf][ak+0][am] = ra2.x; As[buf][ak+1][am] = ra2.y;
            As[buf][ak+2][am] = ra2.z; As[buf][ak+3][am] = ra2.w;
            #pragma unroll
            for (int i = 0; i < 4; i++) Bs[buf][bk][bn0+i] = rb2[i];
            __syncthreads();
        }
    }
    #pragma unroll
    for (int i = 0; i < 8; i++) {
        size_t m = bm + tr*8 + i;
        #pragma unroll
        for (int j = 0; j < 8; j++) {
            int n = bn + tc*8 + j;
            if (n < N) {
                float v = acc[i][j];
                if (bias) v += bias[n];
                C[m * ldc + n] = v;
            }
        }
    }
}

// ---------------- small-N SGEMM (kept for x_proj, N=34) ----------------
__global__ void sgemm_k(const float* __restrict__ A, const float* __restrict__ B,
                        float* __restrict__ C, const float* __restrict__ bias,
                        int N, int K, int lda, int ldb, int ldc) {
    __shared__ float As[16][128];
    __shared__ float Bs[16][64];
    const int bm = blockIdx.y * 128, bn = blockIdx.x * 64;
    const int tid = threadIdx.x;
    const int tr = tid >> 4, tc = tid & 15;
    float acc[8][4];
    #pragma unroll
    for (int i = 0; i < 8; i++)
        #pragma unroll
        for (int j = 0; j < 4; j++) acc[i][j] = 0.f;

    for (int k0 = 0; k0 < K; k0 += 16) {
        #pragma unroll
        for (int i = 0; i < 2; i++) {
            int idx = tid + i * 256;
            int r = idx >> 2, c4 = (idx & 3) * 4;
            float4 v = *(const float4*)(A + (size_t)(bm + r) * lda + k0 + c4);
            As[c4+0][r]=v.x; As[c4+1][r]=v.y; As[c4+2][r]=v.z; As[c4+3][r]=v.w;
        }
        {
            int r = tid >> 4, c0 = (tid & 15) * 4;
            #pragma unroll
            for (int i = 0; i < 4; i++) {
                int n = bn + c0 + i;
                Bs[r][c0+i] = (n < N) ? B[(size_t)(k0 + r) * ldb + n] : 0.f;
            }
        }
        __syncthreads();
        #pragma unroll
        for (int kk = 0; kk < 16; kk++) {
            float4 a0 = *(const float4*)&As[kk][tr*8];
            float4 a1 = *(const float4*)&As[kk][tr*8+4];
            float4 b0 = *(const float4*)&Bs[kk][tc*4];
            float a[8] = {a0.x,a0.y,a0.z,a0.w,a1.x,a1.y,a1.z,a1.w};
            float b[4] = {b0.x,b0.y,b0.z,b0.w};
            #pragma unroll
            for (int i = 0; i < 8; i++)
                #pragma unroll
                for (int j = 0; j < 4; j++) acc[i][j] += a[i]*b[j];
        }
        __syncthreads();
    }
    #pragma unroll
    for (int i = 0; i < 8; i++) {
        int m = bm + tr*8 + i;
        #pragma unroll
        for (int j = 0; j < 4; j++) {
            int n = bn + tc*4 + j;
            if (n < N) {
                float v = acc[i][j];
                if (bias) v += bias[n];
                C[(size_t)m * ldc + n] = v;
            }
        }
    }
}

// ---------------- stage 1: channel attention ----------------
__global__ void k_gram(const float* __restrict__ q, const float* __restrict__ kv,
                       float* __restrict__ attn) {
    int b = blockIdx.x, h = blockIdx.y;
    __shared__ float kt[32][28], qt[32][28];
    __shared__ float G[840];
    int tid = threadIdx.x;   // 256
    float acc[4] = {0.f,0.f,0.f,0.f};
    for (int nt = 0; nt < 40; nt++) {
        for (int idx = tid; idx < 896; idx += 256) {
            int n = idx / 28, i = idx % 28;
            size_t row = (size_t)b*1280 + nt*32 + n;
            kt[n][i] = kv[row*448 + h*28 + i];
            qt[n][i] = q [row*224 + h*28 + i];
        }
        __syncthreads();
        #pragma unroll
        for (int s = 0; s < 4; s++) {
            int w = tid + 256*s;
            if (w < 784) {
                int i = w/28, j = w%28; float a = acc[s];
                #pragma unroll
                for (int n = 0; n < 32; n++) a += kt[n][i]*qt[n][j];
                acc[s] = a;
            } else if (w < 812) {
                int i = w - 784; float a = acc[s];
                #pragma unroll
                for (int n = 0; n < 32; n++) a += kt[n][i]*kt[n][i];
                acc[s] = a;
            } else if (w < 840) {
                int j = w - 812; float a = acc[s];
                #pragma unroll
                for (int n = 0; n < 32; n++) a += qt[n][j]*qt[n][j];
                acc[s] = a;
            }
        }
        __syncthreads();
    }
    #pragma unroll
    for (int s = 0; s < 4; s++) { int w = tid + 256*s; if (w < 840) G[w] = acc[s]; }
    __syncthreads();
    if (tid < 28) {
        int i = tid;
        float nk = fmaxf(sqrtf(G[784+i]), 1e-12f);
        float lg[28], m = -1e30f;
        #pragma unroll
        for (int j = 0; j < 28; j++) {
            float nq = fmaxf(sqrtf(G[812+j]), 1e-12f);
            lg[j] = G[i*28+j] / (nk*nq) * 0.18898223650461363f;
            m = fmaxf(m, lg[j]);
        }
        float sum = 0.f;
        #pragma unroll
        for (int j = 0; j < 28; j++) { lg[j] = __expf(lg[j]-m); sum += lg[j]; }
        float inv = 1.f/sum;
        #pragma unroll
        for (int j = 0; j < 28; j++)
            attn[(((size_t)b*8 + h)*28 + i)*28 + j] = lg[j]*inv;
    }
}

// x1 = attn-applied + residual; 4 rows per barrier interval
__global__ void k_apply(const float* __restrict__ x, const float* __restrict__ kv,
                        const float* __restrict__ attn, float* __restrict__ x1) {
    int chunk = blockIdx.x, b = blockIdx.y;
    __shared__ float att[6272];
    __shared__ float vr[4][224];
    int tid = threadIdx.x;   // 224
    for (int idx = tid; idx < 6272; idx += 224) att[idx] = attn[(size_t)b*6272 + idx];
    int h = tid / 28, i = tid % 28;
    for (int nn = 0; nn < 64; nn += 4) {
        size_t row0 = (size_t)b*1280 + chunk*64 + nn;
        __syncthreads();
        for (int idx = tid; idx < 896; idx += 224) {
            int rr = idx / 224, cc = idx % 224;
            vr[rr][cc] = kv[(row0 + rr)*448 + 224 + cc];
        }
        __syncthreads();
        #pragma unroll
        for (int rr = 0; rr < 4; rr++) {
            float a = 0.f;
            #pragma unroll
            for (int j = 0; j < 28; j++) a += att[(h*28+i)*28 + j] * vr[rr][h*28 + j];
            size_t o = (row0 + rr)*224 + tid;
            x1[o] = x[o] + a;
        }
    }
}

// ---------------- transpose + LN into (b, L=8960, 32) ----------------
__global__ void k_ln1(const float* __restrict__ x1, const float* __restrict__ g,
                      const float* __restrict__ be, float* __restrict__ xn) {
    int ww = blockIdx.x, b = blockIdx.y;
    __shared__ float s[32*225];
    int tid = threadIdx.x;   // 256
    for (int idx = tid; idx < 32*224; idx += 256) {
        int m = idx / 224, cc = idx % 224;
        s[m*225 + cc] = x1[((size_t)b*1280 + m*40 + ww)*224 + cc];
    }
    __syncthreads();
    for (int cc = tid; cc < 224; cc += 256) {
        float mean = 0.f;
        #pragma unroll
        for (int m = 0; m < 32; m++) mean += s[m*225+cc];
        mean *= (1.f/32.f);
        float var = 0.f;
        #pragma unroll
        for (int m = 0; m < 32; m++) { float d = s[m*225+cc]-mean; var += d*d; }
        var *= (1.f/32.f);
        float inv = rsqrtf(var + 1e-5f);
        size_t ob = ((size_t)b*8960 + ww*224 + cc)*32;
        #pragma unroll
        for (int m = 0; m < 32; m++)
            xn[ob + m] = (s[m*225+cc]-mean)*inv*g[m] + be[m];
    }
}

// ---------------- mamba pieces ----------------
__global__ void k_conv1d(const float* __restrict__ xz, const float* __restrict__ cw,
                         const float* __restrict__ cb, float* __restrict__ xc) {
    size_t id = (size_t)blockIdx.x*256 + threadIdx.x;
    size_t row = id >> 6; int d = (int)(id & 63);
    size_t b = row / 8960; int l = (int)(row % 8960);
    float acc = cb[d];
    #pragma unroll
    for (int t = 0; t < 4; t++) {
        int ls = l - 3 + t;
        if (ls >= 0) acc += xz[((size_t)b*8960 + ls)*128 + d] * cw[d*4 + t];
    }
    xc[row*64 + d] = siluf(acc);
}

__global__ void k_dtbc(const float* __restrict__ xdbl, const float* __restrict__ dtW,
                       const float* __restrict__ dtb, float* __restrict__ dt,
                       float* __restrict__ Bm, float* __restrict__ Cm) {
    size_t id = (size_t)blockIdx.x*256 + threadIdx.x;
    size_t row = id / 96; int j = (int)(id % 96);
    const float* xd = xdbl + row*34;
    if (j < 64) {
        float v = xd[0]*dtW[j] + xd[1]*dtW[64+j] + dtb[j];
        dt[row*64 + j] = (v > 20.f) ? v : log1pf(__expf(v));
    } else if (j < 80) {
        Bm[row*16 + (j-64)] = xd[2 + (j-64)];
    } else {
        Cm[row*16 + (j-80)] = xd[18 + (j-80)];
    }
}

__global__ void k_scan1(const float* __restrict__ dt, const float* __restrict__ xc,
                        const float* __restrict__ Bm, const float* __restrict__ Alog,
                        float* __restrict__ S, float* __restrict__ sumdt) {
    int gw = (blockIdx.x*256 + threadIdx.x) >> 5;
    int lane = threadIdx.x & 31;
    int b = gw / 2240; int rem = gw % 2240;
    int chunk = rem >> 5; int dp = rem & 31;
    int d = dp*2 + (lane >> 4); int n = lane & 15;
    float Av = -__expf(Alog[d*16 + n]);
    float h = 0.f, sdt = 0.f;
    size_t base = (size_t)b*8960 + chunk*128;
    for (int l = 0; l < 128; l++) {
        size_t row = base + l;
        float dtv = dt[row*64 + d];
        float u   = xc[row*64 + d];
        float Bn  = Bm[row*16 + n];
        h = __expf(Av*dtv)*h + dtv*u*Bn;
        sdt += dtv;
    }
    size_t idx = (size_t)(b*64 + d)*70 + chunk;
    S[idx*16 + n] = h;
    if (n == 0) sumdt[idx] = sdt;
}

__global__ void k_scan2(const float* __restrict__ S, const float* __restrict__ sumdt,
                        const float* __restrict__ Alog, float* __restrict__ H0) {
    int t = blockIdx.x*256 + threadIdx.x;
    int b = t >> 10; int d = (t >> 4) & 63; int n = t & 15;
    float Av = -__expf(Alog[d*16 + n]);
    float carry = 0.f;
    size_t base = (size_t)(b*64 + d)*70;
    for (int ch = 0; ch < 70; ch++) {
        size_t idx = base + ch;
        H0[idx*16 + n] = carry;
        carry = carry*__expf(Av*sumdt[idx]) + S[idx*16 + n];
    }
}

__global__ void k_scan3(const float* __restrict__ dt, const float* __restrict__ xc,
                        const float* __restrict__ Bm, const float* __restrict__ Cm,
                        const float* __restrict__ Alog, const float* __restrict__ H0,
                        float* __restrict__ y) {
    int gw = (blockIdx.x*256 + threadIdx.x) >> 5;
    int lane = threadIdx.x & 31;
    int b = gw / 2240; int rem = gw % 2240;
    int chunk = rem >> 5; int dp = rem & 31;
    int d = dp*2 + (lane >> 4); int n = lane & 15;
    float Av = -__expf(Alog[d*16 + n]);
    size_t idx = (size_t)(b*64 + d)*70 + chunk;
    float h = H0[idx*16 + n];
    size_t base = (size_t)b*8960 + chunk*128;
    for (int l = 0; l < 128; l++) {
        size_t row = base + l;
        float dtv = dt[row*64 + d];
        float u   = xc[row*64 + d];
        float Bn  = Bm[row*16 + n];
        h = __expf(Av*dtv)*h + dtv*u*Bn;
        float yv = h * Cm[row*16 + n];
        yv += __shfl_xor_sync(0xffffffffu, yv, 8);
        yv += __shfl_xor_sync(0xffffffffu, yv, 4);
        yv += __shfl_xor_sync(0xffffffffu, yv, 2);
        yv += __shfl_xor_sync(0xffffffffu, yv, 1);
        if (n == 0) y[row*64 + d] = yv;
    }
}

__global__ void k_final(const float* __restrict__ y, const float* __restrict__ xc,
                        const float* __restrict__ xz, const float* __restrict__ xn,
                        const float* __restrict__ Dp, const float* __restrict__ opW,
                        const float* __restrict__ skipp, const float* __restrict__ g,
                        const float* __restrict__ be, const float* __restrict__ projW,
                        const float* __restrict__ projb, float* __restrict__ xm2) {
    __shared__ float sop[2048], spj[1024];
    int tid = threadIdx.x;   // 256
    for (int i = tid; i < 2048; i += 256) sop[i] = opW[i];
    for (int i = tid; i < 1024; i += 256) spj[i] = projW[i];
    __syncthreads();
    int warp = tid >> 5, lane = tid & 31;
    size_t r = (size_t)blockIdx.x*8 + warp;
    float skip = skipp[0];
    float y0 = y[r*64 + lane],      y1 = y[r*64 + 32 + lane];
    float c0 = xc[r*64 + lane],     c1 = xc[r*64 + 32 + lane];
    float z0 = xz[r*128 + 64 + lane], z1 = xz[r*128 + 96 + lane];
    float yy0 = (y0 + c0*Dp[lane])    * siluf(z0);
    float yy1 = (y1 + c1*Dp[32+lane]) * siluf(z1);
    float acc = 0.f;
    #pragma unroll
    for (int d = 0; d < 32; d++) acc += __shfl_sync(0xffffffffu, yy0, d) * sop[d*32 + lane];
    #pragma unroll
    for (int d = 0; d < 32; d++) acc += __shfl_sync(0xffffffffu, yy1, d) * sop[(d+32)*32 + lane];
    float xm = acc + skip * xn[r*32 + lane];
    float mean = xm;
    #pragma unroll
    for (int o = 16; o; o >>= 1) mean += __shfl_xor_sync(0xffffffffu, mean, o);
    mean *= (1.f/32.f);
    float dv = xm - mean, var = dv*dv;
    #pragma unroll
    for (int o = 16; o; o >>= 1) var += __shfl_xor_sync(0xffffffffu, var, o);
    var *= (1.f/32.f);
    float v = dv * rsqrtf(var + 1e-5f) * g[lane] + be[lane];
    float acc2 = projb[lane];
    #pragma unroll
    for (int mm = 0; mm < 32; mm++) acc2 += __shfl_sync(0xffffffffu, v, mm) * spj[mm*32 + lane];
    xm2[r*32 + lane] = acc2;
}

__global__ void k_addback(const float* __restrict__ x1, const float* __restrict__ xm2,
                          float* __restrict__ x2) {
    int ww = blockIdx.x, b = blockIdx.y;
    __shared__ float s[224*33];
    int tid = threadIdx.x;   // 256
    for (int idx = tid; idx < 224*32; idx += 256) {
        int cc = idx >> 5, m = idx & 31;
        s[cc*33 + m] = xm2[((size_t)b*8960 + ww*224 + cc)*32 + m];
    }
    __syncthreads();
    for (int idx = tid; idx < 32*224; idx += 256) {
        int m = idx / 224, cc = idx % 224;
        size_t o = ((size_t)b*1280 + m*40 + ww)*224 + cc;
        x2[o] = x1[o] + s[cc*33 + m];
    }
}

// ---------------- conv3d 5x5x5, pad 2 ----------------
__global__ void k_conv3d(const float* __restrict__ x2, const float* __restrict__ cw,
                         const float* __restrict__ cb, float* __restrict__ x3) {
    int y = blockIdx.x, b = blockIdx.y;
    int xx = threadIdx.x;   // 224
    __shared__ float ws[125];
    if (xx < 125) ws[xx] = cw[xx];
    __syncthreads();
    float acc[32];
    #pragma unroll
    for (int d = 0; d < 32; d++) acc[d] = 0.f;
    for (int ky = 0; ky < 5; ky++) {
        int yy = y + ky - 2;
        if (yy < 0 || yy >= 40) continue;
        for (int kx = 0; kx < 5; kx++) {
            int x2i = xx + kx - 2;
            if (x2i < 0 || x2i >= 224) continue;
            float v[36];
            v[0]=v[1]=v[34]=v[35]=0.f;
            #pragma unroll
            for (int i = 2; i < 34; i++)
                v[i] = x2[(((size_t)b*32 + (i-2))*40 + yy)*224 + x2i];
            #pragma unroll
            for (int kz = 0; kz < 5; kz++) {
                float wv = ws[(kz*5 + ky)*5 + kx];
                #pragma unroll
                for (int d = 0; d < 32; d++) acc[d] += v[d+kz]*wv;
            }
        }
    }
    float bias = cb[0];
    #pragma unroll
    for (int d = 0; d < 32; d++)
        x3[(((size_t)b*32 + d)*40 + y)*224 + xx] = acc[d] + bias;
}

// ---------------- DWT + reflect-pad + window pack ----------------
__global__ void k_dwt(const float* __restrict__ x3, float* __restrict__ xw) {
    size_t id = (size_t)blockIdx.x*256 + threadIdx.x;   // 11010048
    int c = (int)(id % 224); size_t r = id / 224;
    int sub = (int)(r / 12288); int rw = (int)(r % 12288);
    int win = rw >> 6, tok = rw & 63;
    int bb = win / 6, w6 = win % 6;
    int wi = w6 / 3, wj = w6 % 3;
    int ti = tok >> 3, tj = tok & 7;
    int i2 = wi*8 + ti;
    int j2 = wj*8 + tj;
    int j = (j2 < 20) ? j2 : 38 - j2;   // reflect pad
    size_t base = (((size_t)bb*32 + 2*i2)*40 + 2*j)*224 + c;
    float a  = x3[base],        bv = x3[base + 224];
    float c2 = x3[base + 8960], d2 = x3[base + 9184];
    float val;
    if      (sub == 0) val = a + bv + c2 + d2;
    else if (sub == 1) val = a + bv - c2 - d2;
    else if (sub == 2) val = a - bv + c2 - d2;
    else               val = a - bv - c2 + d2;
    xw[id] = 0.5f * val;
}

// ---------------- window attention ----------------
__global__ void k_wattn(const float* __restrict__ qkvw, const float* __restrict__ pe,
                        float* __restrict__ obuf) {
    int win = blockIdx.x, head = blockIdx.y;
    __shared__ float qs[64*28], ks[64*28], vs[64*28];
    __shared__ float lgs[64*65];
    int tid = threadIdx.x;   // 64
    size_t wbase = (size_t)win * 64;
    for (int idx = tid; idx < 1792; idx += 64) {
        int tok = idx / 28, dd = idx % 28;
        size_t rb = (wbase + tok)*672 + head*28 + dd;
        qs[idx] = qkvw[rb] * 0.18898223650461363f;
        ks[idx] = qkvw[rb + 224];
        vs[idx] = qkvw[rb + 448];
    }
    __syncthreads();
    int i = tid;
    float qr[28];
    #pragma unroll
    for (int dd = 0; dd < 28; dd++) qr[dd] = qs[i*28 + dd];
    const float* per = pe + ((size_t)head*64 + i)*64;
    float m = -1e30f;
    for (int j = 0; j < 64; j++) {
        float dot = 0.f;
        #pragma unroll
        for (int dd = 0; dd < 28; dd++) dot += qr[dd]*ks[j*28 + dd];
        float l = dot + per[j];
        lgs[i*65 + j] = l;
        m = fmaxf(m, l);
    }
    float sum = 0.f;
    for (int j = 0; j < 64; j++) {
        float e = __expf(lgs[i*65 + j] - m);
        lgs[i*65 + j] = e;
        sum += e;
    }
    float inv = 1.f / sum;
    float acc[28];
    #pragma unroll
    for (int dd = 0; dd < 28; dd++) acc[dd] = 0.f;
    for (int j = 0; j < 64; j++) {
        float a = lgs[i*65 + j] * inv;
        #pragma unroll
        for (int dd = 0; dd < 28; dd++) acc[dd] += a*vs[j*28 + dd];
    }
    size_t ob = (wbase + i)*224 + head*28;
    #pragma unroll
    for (int dd = 0; dd < 28; dd++) obuf[ob + dd] = acc[dd];
}

// ---------------- IWT + crop + final layout ----------------
__global__ void k_iwt(const float* __restrict__ oproj, float* __restrict__ out) {
    size_t id = (size_t)blockIdx.x*256 + threadIdx.x;   // 2293760
    int c = (int)(id % 224); size_t r = id / 224;
    int j = (int)(r % 20); r /= 20;
    int i = (int)(r % 16); int bb = (int)(r / 16);
    int wi = i >> 3, ti = i & 7, wj = j >> 3, tj = j & 7;
    size_t row0 = ((size_t)(bb*6 + wi*3 + wj))*64 + ti*8 + tj;
    float A  = oproj[row0*224 + c];
    float Hh = oproj[(row0 + 12288)*224 + c];
    float V  = oproj[(row0 + 24576)*224 + c];
    float D  = oproj[(row0 + 36864)*224 + c];
    size_t oo = (((size_t)bb*32 + 2*i)*40 + 2*j)*224 + c;
    out[oo]          = 0.5f*(A + Hh + V + D);
    out[oo + 224]    = 0.5f*(A + Hh - V - D);
    out[oo + 8960]   = 0.5f*(A - Hh + V - D);
    out[oo + 9184]   = 0.5f*(A - Hh - V + D);
}

// ---------------- launcher ----------------
extern "C" void kernel_launch(void* const* d_in, const int* in_sizes, int n_in,
                              void* d_out, int out_size) {
    const float* x       = (const float*)d_in[0];
    const float* Wq      = (const float*)d_in[1];
    const float* Wkv     = (const float*)d_in[2];
    const float* ln_g    = (const float*)d_in[3];
    const float* ln_b    = (const float*)d_in[4];
    const float* in_proj = (const float*)d_in[5];
    const float* conv1dW = (const float*)d_in[6];
    const float* conv1db = (const float*)d_in[7];
    const float* x_projW = (const float*)d_in[8];
    const float* dt_projW= (const float*)d_in[9];
    const float* dt_projb= (const float*)d_in[10];
    const float* A_log   = (const float*)d_in[11];
    const float* Dp      = (const float*)d_in[12];
    const float* out_projW=(const float*)d_in[13];
    const float* skip    = (const float*)d_in[14];
    const float* projW   = (const float*)d_in[15];
    const float* projb   = (const float*)d_in[16];
    const float* conv3dW = (const float*)d_in[17];
    const float* conv3db = (const float*)d_in[18];
    const float* Wq1     = (const float*)d_in[19];
    const float* Wkv1    = (const float*)d_in[20];
    const float* pos_emb = (const float*)d_in[21];
    const float* Wo[4]   = {(const float*)d_in[22],(const float*)d_in[24],
                            (const float*)d_in[26],(const float*)d_in[28]};
    const float* bo[4]   = {(const float*)d_in[23],(const float*)d_in[25],
                            (const float*)d_in[27],(const float*)d_in[29]};
    float* out = (float*)d_out;

    float *p_q, *p_kv, *p_attn, *p_x1, *p_xn, *p_xz, *p_xc, *p_xdbl, *p_dt,
          *p_Bm, *p_Cm, *p_y, *p_S, *p_sd, *p_H0, *p_xm2, *p_x2, *p_x3,
          *p_xw, *p_qkvw, *p_obuf, *p_oproj;
    cudaGetSymbolAddress((void**)&p_q,    g_q);
    cudaGetSymbolAddress((void**)&p_kv,   g_kv);
    cudaGetSymbolAddress((void**)&p_attn, g_attn);
    cudaGetSymbolAddress((void**)&p_x1,   g_x1);
    cudaGetSymbolAddress((void**)&p_xn,   g_xn);
    cudaGetSymbolAddress((void**)&p_xz,   g_xz);
    cudaGetSymbolAddress((void**)&p_xc,   g_xc);
    cudaGetSymbolAddress((void**)&p_xdbl, g_xdbl);
    cudaGetSymbolAddress((void**)&p_dt,   g_dt);
    cudaGetSymbolAddress((void**)&p_Bm,   g_Bm);
    cudaGetSymbolAddress((void**)&p_Cm,   g_Cm);
    cudaGetSymbolAddress((void**)&p_y,    g_y);
    cudaGetSymbolAddress((void**)&p_S,    g_S);
    cudaGetSymbolAddress((void**)&p_sd,   g_sumdt);
    cudaGetSymbolAddress((void**)&p_H0,   g_H0);
    cudaGetSymbolAddress((void**)&p_xm2,  g_xm2);
    cudaGetSymbolAddress((void**)&p_x2,   g_x2);
    cudaGetSymbolAddress((void**)&p_x3,   g_x3);
    cudaGetSymbolAddress((void**)&p_xw,   g_xw);
    cudaGetSymbolAddress((void**)&p_qkvw, g_qkvw);
    cudaGetSymbolAddress((void**)&p_obuf, g_obuf);
    cudaGetSymbolAddress((void**)&p_oproj,g_oproj);

    // stage 1: q/kv GEMMs, gram+softmax, apply
    sgemm128<<<dim3(2, 320), 256>>>(x, Wq,  p_q,  nullptr, 224, 224, 224, 224, 224);
    sgemm128<<<dim3(4, 320), 256>>>(x, Wkv, p_kv, nullptr, 448, 224, 224, 448, 448);
    k_gram <<<dim3(32, 8), 256>>>(p_q, p_kv, p_attn);
    k_apply<<<dim3(20, 32), 224>>>(x, p_kv, p_attn, p_x1);

    // stage 2: mamba
    k_ln1<<<dim3(40, 32), 256>>>(p_x1, ln_g, ln_b, p_xn);
    sgemm128<<<dim3(1, 2240), 256>>>(p_xn, in_proj, p_xz, nullptr, 128, 32, 32, 128, 128);
    k_conv1d<<<71680, 256>>>(p_xz, conv1dW, conv1db, p_xc);
    sgemm_k<<<dim3(1, 2240), 256>>>(p_xc, x_projW, p_xdbl, nullptr, 34, 64, 64, 34, 34);
    k_dtbc<<<107520, 256>>>(p_xdbl, dt_projW, dt_projb, p_dt, p_Bm, p_Cm);
    k_scan1<<<8960, 256>>>(p_dt, p_xc, p_Bm, A_log, p_S, p_sd);
    k_scan2<<<128, 256>>>(p_S, p_sd, A_log, p_H0);
    k_scan3<<<8960, 256>>>(p_dt, p_xc, p_Bm, p_Cm, A_log, p_H0, p_y);
    k_final<<<35840, 256>>>(p_y, p_xc, p_xz, p_xn, Dp, out_projW, skip,
                            ln_g, ln_b, projW, projb, p_xm2);
    k_addback<<<dim3(40, 32), 256>>>(p_x1, p_xm2, p_x2);

    // stage 3: conv3d
    k_conv3d<<<dim3(40, 32), 224>>>(p_x2, conv3dW, conv3db, p_x3);

    // stage 4: DWT + window attention
    k_dwt<<<43008, 256>>>(p_x3, p_xw);
    sgemm128<<<dim3(2, 384), 256>>>(p_xw, Wq1,  p_qkvw,       nullptr, 224, 224, 224, 224, 672);
    sgemm128<<<dim3(4, 384), 256>>>(p_xw, Wkv1, p_qkvw + 224, nullptr, 448, 224, 224, 448, 672);
    k_wattn<<<dim3(768, 8), 64>>>(p_qkvw, pos_emb, p_obuf);
    for (int s = 0; s < 4; s++) {
        sgemm128<<<dim3(2, 96), 256>>>(p_obuf + (size_t)s*12288*224, Wo[s],
                                       p_oproj + (size_t)s*12288*224, bo[s],
                                       224, 224, 224, 224, 224);
    }

    // stage 5: IWT + output
    k_iwt<<<8960, 256>>>(p_oproj, out);
}

// round 5
// speedup vs baseline: 1.3321x; 1.0048x over previous
#include <cuda_runtime.h>
#include <math.h>
#include <stdint.h>

// ---------------- static scratch (16B aligned for float4 paths) ----------------
__device__ __align__(16) float g_q    [40960u*224u];
__device__ __align__(16) float g_kv   [40960u*448u];
__device__ __align__(16) float g_attn [32*8*28*28];
__device__ __align__(16) float g_x1   [9175040];
__device__ __align__(16) float g_xn   [9175040];      // 286720 x 32
__device__ __align__(16) float g_xz   [36700160];     // 286720 x 128
__device__ __align__(16) float g_xc   [18350080];     // 286720 x 64
__device__ __align__(16) float g_xdbl [9748480];      // 286720 x 34
__device__ __align__(16) float g_dt   [18350080];
__device__ __align__(16) float g_Bm   [4587520];
__device__ __align__(16) float g_Cm   [4587520];
__device__ __align__(16) float g_y    [18350080];
__device__ __align__(16) float g_S    [2293760];      // 32*64*70*16
__device__ __align__(16) float g_sumdt[143360];       // 32*64*70
__device__ __align__(16) float g_H0   [2293760];
__device__ __align__(16) float g_xm2  [9175040];      // 286720 x 32
__device__ __align__(16) float g_x2   [9175040];
__device__ __align__(16) float g_x3   [9175040];
__device__ __align__(16) float g_xw   [11010048];     // 49152 x 224
__device__ __align__(16) float g_qkvw [33030144];     // 49152 x 672
__device__ __align__(16) float g_obuf [11010048];
__device__ __align__(16) float g_oproj[11010048];

__device__ __forceinline__ float siluf(float v){ return v / (1.f + __expf(-v)); }

struct GemmPtrs4 { const float* B[4]; const float* bias[4]; };

// ---------------- big SGEMM core: 128x128 tile, 8x8 micro, BK=8, double-buffered
// Requires M % 128 == 0, K % 8 == 0, lda % 4 == 0, A 16B-aligned. N predicated.
__device__ __forceinline__ void sgemm128_core(
    const float* __restrict__ A, const float* __restrict__ B,
    float* __restrict__ C, const float* __restrict__ bias,
    int N, int K, int lda, int ldb, int ldc,
    float (*As)[8][128], float (*Bs)[8][128])
{
    const int bm = blockIdx.y * 128;
    const int bn = blockIdx.x * 128;
    const int tid = threadIdx.x;
    const int tr = tid >> 4, tc = tid & 15;
    const int am = tid >> 1;
    const int ak = (tid & 1) * 4;
    const int bk  = tid >> 5;
    const int bn0 = (tid & 31) * 4;

    const float* Aptr = A + (size_t)(bm + am) * lda + ak;
    const float* Bptr = B + (size_t)bk * ldb + bn + bn0;

    float acc[8][8];
    #pragma unroll
    for (int i = 0; i < 8; i++)
        #pragma unroll
        for (int j = 0; j < 8; j++) acc[i][j] = 0.f;

    float4 ra = *(const float4*)Aptr;
    float rb[4];
    #pragma unroll
    for (int i = 0; i < 4; i++) {
        int n = bn + bn0 + i;
        rb[i] = (n < N) ? Bptr[i] : 0.f;
    }
    int buf = 0;
    As[0][ak+0][am] = ra.x; As[0][ak+1][am] = ra.y;
    As[0][ak+2][am] = ra.z; As[0][ak+3][am] = ra.w;
    #pragma unroll
    for (int i = 0; i < 4; i++) Bs[0][bk][bn0+i] = rb[i];
    __syncthreads();

    for (int k0 = 0; k0 < K; k0 += 8) {
        const bool more = (k0 + 8) < K;
        float4 ra2; float rb2[4];
        if (more) {
            ra2 = *(const float4*)(Aptr + k0 + 8);
            const float* bp = Bptr + (size_t)(k0 + 8) * ldb;
            #pragma unroll
            for (int i = 0; i < 4; i++) {
                int n = bn + bn0 + i;
                rb2[i] = (n < N) ? bp[i] : 0.f;
            }
        }
        #pragma unroll
        for (int kk = 0; kk < 8; kk++) {
            float a[8], b[8];
            *(float4*)&a[0] = *(const float4*)&As[buf][kk][tr*8];
            *(float4*)&a[4] = *(const float4*)&As[buf][kk][tr*8+4];
            *(float4*)&b[0] = *(const float4*)&Bs[buf][kk][tc*8];
            *(float4*)&b[4] = *(const float4*)&Bs[buf][kk][tc*8+4];
            #pragma unroll
            for (int i = 0; i < 8; i++)
                #pragma unroll
                for (int j = 0; j < 8; j++) acc[i][j] += a[i]*b[j];
        }
        if (more) {
            buf ^= 1;
            As[buf][ak+0][am] = ra2.x; As[buf][ak+1][am] = ra2.y;
            As[buf][ak+2][am] = ra2.z; As[buf][ak+3][am] = ra2.w;
            #pragma unroll
            for (int i = 0; i < 4; i++) Bs[buf][bk][bn0+i] = rb2[i];
            __syncthreads();
        }
    }
    #pragma unroll
    for (int i = 0; i < 8; i++) {
        size_t m = bm + tr*8 + i;
        #pragma unroll
        for (int j = 0; j < 8; j++) {
            int n = bn + tc*8 + j;
            if (n < N) {
                float v = acc[i][j];
                if (bias) v += bias[n];
                C[m * ldc + n] = v;
            }
        }
    }
}

__global__ __launch_bounds__(256, 2) void sgemm128(
    const float* __restrict__ A, const float* __restrict__ B,
    float* __restrict__ C, const float* __restrict__ bias,
    int N, int K, int lda, int ldb, int ldc)
{
    __shared__ float As[2][8][128];
    __shared__ float Bs[2][8][128];
    sgemm128_core(A, B, C, bias, N, K, lda, ldb, ldc, As, Bs);
}

// batched variant: per-z B/bias, A and C strided by z
__global__ __launch_bounds__(256, 2) void sgemm128_b4(
    const float* __restrict__ A, GemmPtrs4 p, float* __restrict__ C,
    int N, int K, int lda, int ldb, int ldc,
    long long strideA, long long strideC)
{
    __shared__ float As[2][8][128];
    __shared__ float Bs[2][8][128];
    int z = blockIdx.z;
    sgemm128_core(A + (size_t)z * strideA, p.B[z], C + (size_t)z * strideC,
                  p.bias[z], N, K, lda, ldb, ldc, As, Bs);
}

// ---------------- small-N SGEMM (kept for x_proj, N=34) ----------------
__global__ void sgemm_k(const float* __restrict__ A, const float* __restrict__ B,
                        float* __restrict__ C, const float* __restrict__ bias,
                        int N, int K, int lda, int ldb, int ldc) {
    __shared__ float As[16][128];
    __shared__ float Bs[16][64];
    const int bm = blockIdx.y * 128, bn = blockIdx.x * 64;
    const int tid = threadIdx.x;
    const int tr = tid >> 4, tc = tid & 15;
    float acc[8][4];
    #pragma unroll
    for (int i = 0; i < 8; i++)
        #pragma unroll
        for (int j = 0; j < 4; j++) acc[i][j] = 0.f;

    for (int k0 = 0; k0 < K; k0 += 16) {
        #pragma unroll
        for (int i = 0; i < 2; i++) {
            int idx = tid + i * 256;
            int r = idx >> 2, c4 = (idx & 3) * 4;
            float4 v = *(const float4*)(A + (size_t)(bm + r) * lda + k0 + c4);
            As[c4+0][r]=v.x; As[c4+1][r]=v.y; As[c4+2][r]=v.z; As[c4+3][r]=v.w;
        }
        {
            int r = tid >> 4, c0 = (tid & 15) * 4;
            #pragma unroll
            for (int i = 0; i < 4; i++) {
                int n = bn + c0 + i;
                Bs[r][c0+i] = (n < N) ? B[(size_t)(k0 + r) * ldb + n] : 0.f;
            }
        }
        __syncthreads();
        #pragma unroll
        for (int kk = 0; kk < 16; kk++) {
            float4 a0 = *(const float4*)&As[kk][tr*8];
            float4 a1 = *(const float4*)&As[kk][tr*8+4];
            float4 b0 = *(const float4*)&Bs[kk][tc*4];
            float a[8] = {a0.x,a0.y,a0.z,a0.w,a1.x,a1.y,a1.z,a1.w};
            float b[4] = {b0.x,b0.y,b0.z,b0.w};
            #pragma unroll
            for (int i = 0; i < 8; i++)
                #pragma unroll
                for (int j = 0; j < 4; j++) acc[i][j] += a[i]*b[j];
        }
        __syncthreads();
    }
    #pragma unroll
    for (int i = 0; i < 8; i++) {
        int m = bm + tr*8 + i;
        #pragma unroll
        for (int j = 0; j < 4; j++) {
            int n = bn + tc*4 + j;
            if (n < N) {
                float v = acc[i][j];
                if (bias) v += bias[n];
                C[(size_t)m * ldc + n] = v;
            }
        }
    }
}

// ---------------- stage 1: channel attention ----------------
__global__ void k_gram(const float* __restrict__ q, const float* __restrict__ kv,
                       float* __restrict__ attn) {
    int b = blockIdx.x, h = blockIdx.y;
    __shared__ float kt[32][28], qt[32][28];
    __shared__ float G[840];
    int tid = threadIdx.x;   // 256
    float acc[4] = {0.f,0.f,0.f,0.f};
    for (int nt = 0; nt < 40; nt++) {
        for (int idx = tid; idx < 896; idx += 256) {
            int n = idx / 28, i = idx % 28;
            size_t row = (size_t)b*1280 + nt*32 + n;
            kt[n][i] = kv[row*448 + h*28 + i];
            qt[n][i] = q [row*224 + h*28 + i];
        }
        __syncthreads();
        #pragma unroll
        for (int s = 0; s < 4; s++) {
            int w = tid + 256*s;
            if (w < 784) {
                int i = w/28, j = w%28; float a = acc[s];
                #pragma unroll
                for (int n = 0; n < 32; n++) a += kt[n][i]*qt[n][j];
                acc[s] = a;
            } else if (w < 812) {
                int i = w - 784; float a = acc[s];
                #pragma unroll
                for (int n = 0; n < 32; n++) a += kt[n][i]*kt[n][i];
                acc[s] = a;
            } else if (w < 840) {
                int j = w - 812; float a = acc[s];
                #pragma unroll
                for (int n = 0; n < 32; n++) a += qt[n][j]*qt[n][j];
                acc[s] = a;
            }
        }
        __syncthreads();
    }
    #pragma unroll
    for (int s = 0; s < 4; s++) { int w = tid + 256*s; if (w < 840) G[w] = acc[s]; }
    __syncthreads();
    if (tid < 28) {
        int i = tid;
        float nk = fmaxf(sqrtf(G[784+i]), 1e-12f);
        float lg[28], m = -1e30f;
        #pragma unroll
        for (int j = 0; j < 28; j++) {
            float nq = fmaxf(sqrtf(G[812+j]), 1e-12f);
            lg[j] = G[i*28+j] / (nk*nq) * 0.18898223650461363f;
            m = fmaxf(m, lg[j]);
        }
        float sum = 0.f;
        #pragma unroll
        for (int j = 0; j < 28; j++) { lg[j] = __expf(lg[j]-m); sum += lg[j]; }
        float inv = 1.f/sum;
        #pragma unroll
        for (int j = 0; j < 28; j++)
            attn[(((size_t)b*8 + h)*28 + i)*28 + j] = lg[j]*inv;
    }
}

// x1 = attn-applied + residual; 8 rows per barrier interval
__global__ void k_apply(const float* __restrict__ x, const float* __restrict__ kv,
                        const float* __restrict__ attn, float* __restrict__ x1) {
    int chunk = blockIdx.x, b = blockIdx.y;
    __shared__ float att[6272];
    __shared__ float vr[8][224];
    int tid = threadIdx.x;   // 224
    for (int idx = tid; idx < 6272; idx += 224) att[idx] = attn[(size_t)b*6272 + idx];
    int h = tid / 28, i = tid % 28;
    for (int nn = 0; nn < 64; nn += 8) {
        size_t row0 = (size_t)b*1280 + chunk*64 + nn;
        __syncthreads();
        for (int idx = tid; idx < 1792; idx += 224) {
            int rr = idx / 224, cc = idx % 224;
            vr[rr][cc] = kv[(row0 + rr)*448 + 224 + cc];
        }
        __syncthreads();
        #pragma unroll
        for (int rr = 0; rr < 8; rr++) {
            float a = 0.f;
            #pragma unroll
            for (int j = 0; j < 28; j++) a += att[(h*28+i)*28 + j] * vr[rr][h*28 + j];
            size_t o = (row0 + rr)*224 + tid;
            x1[o] = x[o] + a;
        }
    }
}

// ---------------- transpose + LN into (b, L=8960, 32) ----------------
__global__ void k_ln1(const float* __restrict__ x1, const float* __restrict__ g,
                      const float* __restrict__ be, float* __restrict__ xn) {
    int ww = blockIdx.x, b = blockIdx.y;
    __shared__ float s[32*225];
    int tid = threadIdx.x;   // 256
    for (int idx = tid; idx < 32*224; idx += 256) {
        int m = idx / 224, cc = idx % 224;
        s[m*225 + cc] = x1[((size_t)b*1280 + m*40 + ww)*224 + cc];
    }
    __syncthreads();
    for (int cc = tid; cc < 224; cc += 256) {
        float mean = 0.f;
        #pragma unroll
        for (int m = 0; m < 32; m++) mean += s[m*225+cc];
        mean *= (1.f/32.f);
        float var = 0.f;
        #pragma unroll
        for (int m = 0; m < 32; m++) { float d = s[m*225+cc]-mean; var += d*d; }
        var *= (1.f/32.f);
        float inv = rsqrtf(var + 1e-5f);
        size_t ob = ((size_t)b*8960 + ww*224 + cc)*32;
        #pragma unroll
        for (int m = 0; m < 32; m++)
            xn[ob + m] = (s[m*225+cc]-mean)*inv*g[m] + be[m];
    }
}

// ---------------- mamba pieces ----------------
__global__ void k_conv1d(const float* __restrict__ xz, const float* __restrict__ cw,
                         const float* __restrict__ cb, float* __restrict__ xc) {
    size_t id = (size_t)blockIdx.x*256 + threadIdx.x;
    size_t row = id >> 6; int d = (int)(id & 63);
    size_t b = row / 8960; int l = (int)(row % 8960);
    float acc = cb[d];
    #pragma unroll
    for (int t = 0; t < 4; t++) {
        int ls = l - 3 + t;
        if (ls >= 0) acc += xz[((size_t)b*8960 + ls)*128 + d] * cw[d*4 + t];
    }
    xc[row*64 + d] = siluf(acc);
}

__global__ void k_dtbc(const float* __restrict__ xdbl, const float* __restrict__ dtW,
                       const float* __restrict__ dtb, float* __restrict__ dt,
                       float* __restrict__ Bm, float* __restrict__ Cm) {
    size_t id = (size_t)blockIdx.x*256 + threadIdx.x;
    size_t row = id / 96; int j = (int)(id % 96);
    const float* xd = xdbl + row*34;
    if (j < 64) {
        float v = xd[0]*dtW[j] + xd[1]*dtW[64+j] + dtb[j];
        dt[row*64 + j] = (v > 20.f) ? v : log1pf(__expf(v));
    } else if (j < 80) {
        Bm[row*16 + (j-64)] = xd[2 + (j-64)];
    } else {
        Cm[row*16 + (j-80)] = xd[18 + (j-80)];
    }
}

__global__ void k_scan1(const float* __restrict__ dt, const float* __restrict__ xc,
                        const float* __restrict__ Bm, const float* __restrict__ Alog,
                        float* __restrict__ S, float* __restrict__ sumdt) {
    int gw = (blockIdx.x*256 + threadIdx.x) >> 5;
    int lane = threadIdx.x & 31;
    int b = gw / 2240; int rem = gw % 2240;
    int chunk = rem >> 5; int dp = rem & 31;
    int d = dp*2 + (lane >> 4); int n = lane & 15;
    float Av = -__expf(Alog[d*16 + n]);
    float h = 0.f, sdt = 0.f;
    size_t base = (size_t)b*8960 + chunk*128;
    for (int l = 0; l < 128; l++) {
        size_t row = base + l;
        float dtv = dt[row*64 + d];
        float u   = xc[row*64 + d];
        float Bn  = Bm[row*16 + n];
        h = __expf(Av*dtv)*h + dtv*u*Bn;
        sdt += dtv;
    }
    size_t idx = (size_t)(b*64 + d)*70 + chunk;
    S[idx*16 + n] = h;
    if (n == 0) sumdt[idx] = sdt;
}

__global__ void k_scan2(const float* __restrict__ S, const float* __restrict__ sumdt,
                        const float* __restrict__ Alog, float* __restrict__ H0) {
    int t = blockIdx.x*256 + threadIdx.x;
    int b = t >> 10; int d = (t >> 4) & 63; int n = t & 15;
    float Av = -__expf(Alog[d*16 + n]);
    float carry = 0.f;
    size_t base = (size_t)(b*64 + d)*70;
    for (int ch = 0; ch < 70; ch++) {
        size_t idx = base + ch;
        H0[idx*16 + n] = carry;
        carry = carry*__expf(Av*sumdt[idx]) + S[idx*16 + n];
    }
}

__global__ void k_scan3(const float* __restrict__ dt, const float* __restrict__ xc,
                        const float* __restrict__ Bm, const float* __restrict__ Cm,
                        const float* __restrict__ Alog, const float* __restrict__ H0,
                        float* __restrict__ y) {
    int gw = (blockIdx.x*256 + threadIdx.x) >> 5;
    int lane = threadIdx.x & 31;
    int b = gw / 2240; int rem = gw % 2240;
    int chunk = rem >> 5; int dp = rem & 31;
    int d = dp*2 + (lane >> 4); int n = lane & 15;
    float Av = -__expf(Alog[d*16 + n]);
    size_t idx = (size_t)(b*64 + d)*70 + chunk;
    float h = H0[idx*16 + n];
    size_t base = (size_t)b*8960 + chunk*128;
    for (int l = 0; l < 128; l++) {
        size_t row = base + l;
        float dtv = dt[row*64 + d];
        float u   = xc[row*64 + d];
        float Bn  = Bm[row*16 + n];
        h = __expf(Av*dtv)*h + dtv*u*Bn;
        float yv = h * Cm[row*16 + n];
        yv += __shfl_xor_sync(0xffffffffu, yv, 8);
        yv += __shfl_xor_sync(0xffffffffu, yv, 4);
        yv += __shfl_xor_sync(0xffffffffu, yv, 2);
        yv += __shfl_xor_sync(0xffffffffu, yv, 1);
        if (n == 0) y[row*64 + d] = yv;
    }
}

__global__ void k_final(const float* __restrict__ y, const float* __restrict__ xc,
                        const float* __restrict__ xz, const float* __restrict__ xn,
                        const float* __restrict__ Dp, const float* __restrict__ opW,
                        const float* __restrict__ skipp, const float* __restrict__ g,
                        const float* __restrict__ be, const float* __restrict__ projW,
                        const float* __restrict__ projb, float* __restrict__ xm2) {
    __shared__ float sop[2048], spj[1024];
    int tid = threadIdx.x;   // 256
    for (int i = tid; i < 2048; i += 256) sop[i] = opW[i];
    for (int i = tid; i < 1024; i += 256) spj[i] = projW[i];
    __syncthreads();
    int warp = tid >> 5, lane = tid & 31;
    size_t r = (size_t)blockIdx.x*8 + warp;
    float skip = skipp[0];
    float y0 = y[r*64 + lane],      y1 = y[r*64 + 32 + lane];
    float c0 = xc[r*64 + lane],     c1 = xc[r*64 + 32 + lane];
    float z0 = xz[r*128 + 64 + lane], z1 = xz[r*128 + 96 + lane];
    float yy0 = (y0 + c0*Dp[lane])    * siluf(z0);
    float yy1 = (y1 + c1*Dp[32+lane]) * siluf(z1);
    float acc = 0.f;
    #pragma unroll
    for (int d = 0; d < 32; d++) acc += __shfl_sync(0xffffffffu, yy0, d) * sop[d*32 + lane];
    #pragma unroll
    for (int d = 0; d < 32; d++) acc += __shfl_sync(0xffffffffu, yy1, d) * sop[(d+32)*32 + lane];
    float xm = acc + skip * xn[r*32 + lane];
    float mean = xm;
    #pragma unroll
    for (int o = 16; o; o >>= 1) mean += __shfl_xor_sync(0xffffffffu, mean, o);
    mean *= (1.f/32.f);
    float dv = xm - mean, var = dv*dv;
    #pragma unroll
    for (int o = 16; o; o >>= 1) var += __shfl_xor_sync(0xffffffffu, var, o);
    var *= (1.f/32.f);
    float v = dv * rsqrtf(var + 1e-5f) * g[lane] + be[lane];
    float acc2 = projb[lane];
    #pragma unroll
    for (int mm = 0; mm < 32; mm++) acc2 += __shfl_sync(0xffffffffu, v, mm) * spj[mm*32 + lane];
    xm2[r*32 + lane] = acc2;
}

__global__ void k_addback(const float* __restrict__ x1, const float* __restrict__ xm2,
                          float* __restrict__ x2) {
    int ww = blockIdx.x, b = blockIdx.y;
    __shared__ float s[224*33];
    int tid = threadIdx.x;   // 256
    for (int idx = tid; idx < 224*32; idx += 256) {
        int cc = idx >> 5, m = idx & 31;
        s[cc*33 + m] = xm2[((size_t)b*8960 + ww*224 + cc)*32 + m];
    }
    __syncthreads();
    for (int idx = tid; idx < 32*224; idx += 256) {
        int m = idx / 224, cc = idx % 224;
        size_t o = ((size_t)b*1280 + m*40 + ww)*224 + cc;
        x2[o] = x1[o] + s[cc*33 + m];
    }
}

// ---------------- conv3d 5x5x5, pad 2 ----------------
__global__ void k_conv3d(const float* __restrict__ x2, const float* __restrict__ cw,
                         const float* __restrict__ cb, float* __restrict__ x3) {
    int y = blockIdx.x, b = blockIdx.y;
    int xx = threadIdx.x;   // 224
    __shared__ float ws[125];
    if (xx < 125) ws[xx] = cw[xx];
    __syncthreads();
    float acc[32];
    #pragma unroll
    for (int d = 0; d < 32; d++) acc[d] = 0.f;
    for (int ky = 0; ky < 5; ky++) {
        int yy = y + ky - 2;
        if (yy < 0 || yy >= 40) continue;
        for (int kx = 0; kx < 5; kx++) {
            int x2i = xx + kx - 2;
            if (x2i < 0 || x2i >= 224) continue;
            float v[36];
            v[0]=v[1]=v[34]=v[35]=0.f;
            #pragma unroll
            for (int i = 2; i < 34; i++)
                v[i] = x2[(((size_t)b*32 + (i-2))*40 + yy)*224 + x2i];
            #pragma unroll
            for (int kz = 0; kz < 5; kz++) {
                float wv = ws[(kz*5 + ky)*5 + kx];
                #pragma unroll
                for (int d = 0; d < 32; d++) acc[d] += v[d+kz]*wv;
            }
        }
    }
    float bias = cb[0];
    #pragma unroll
    for (int d = 0; d < 32; d++)
        x3[(((size_t)b*32 + d)*40 + y)*224 + xx] = acc[d] + bias;
}

// ---------------- DWT + reflect-pad + window pack ----------------
__global__ void k_dwt(const float* __restrict__ x3, float* __restrict__ xw) {
    size_t id = (size_t)blockIdx.x*256 + threadIdx.x;   // 11010048
    int c = (int)(id % 224); size_t r = id / 224;
    int sub = (int)(r / 12288); int rw = (int)(r % 12288);
    int win = rw >> 6, tok = rw & 63;
    int bb = win / 6, w6 = win % 6;
    int wi = w6 / 3, wj = w6 % 3;
    int ti = tok >> 3, tj = tok & 7;
    int i2 = wi*8 + ti;
    int j2 = wj*8 + tj;
    int j = (j2 < 20) ? j2 : 38 - j2;   // reflect pad
    size_t base = (((size_t)bb*32 + 2*i2)*40 + 2*j)*224 + c;
    float a  = x3[base],        bv = x3[base + 224];
    float c2 = x3[base + 8960], d2 = x3[base + 9184];
    float val;
    if      (sub == 0) val = a + bv + c2 + d2;
    else if (sub == 1) val = a + bv - c2 - d2;
    else if (sub == 2) val = a - bv + c2 - d2;
    else               val = a - bv - c2 + d2;
    xw[id] = 0.5f * val;
}

// ---------------- window attention ----------------
__global__ void k_wattn(const float* __restrict__ qkvw, const float* __restrict__ pe,
                        float* __restrict__ obuf) {
    int win = blockIdx.x, head = blockIdx.y;
    __shared__ float qs[64*28], ks[64*28], vs[64*28];
    __shared__ float lgs[64*65];
    int tid = threadIdx.x;   // 64
    size_t wbase = (size_t)win * 64;
    for (int idx = tid; idx < 1792; idx += 64) {
        int tok = idx / 28, dd = idx % 28;
        size_t rb = (wbase + tok)*672 + head*28 + dd;
        qs[idx] = qkvw[rb] * 0.18898223650461363f;
        ks[idx] = qkvw[rb + 224];
        vs[idx] = qkvw[rb + 448];
    }
    __syncthreads();
    int i = tid;
    float qr[28];
    #pragma unroll
    for (int dd = 0; dd < 28; dd++) qr[dd] = qs[i*28 + dd];
    const float* per = pe + ((size_t)head*64 + i)*64;
    float m = -1e30f;
    for (int j = 0; j < 64; j++) {
        float dot = 0.f;
        #pragma unroll
        for (int dd = 0; dd < 28; dd++) dot += qr[dd]*ks[j*28 + dd];
        float l = dot + per[j];
        lgs[i*65 + j] = l;
        m = fmaxf(m, l);
    }
    float sum = 0.f;
    for (int j = 0; j < 64; j++) {
        float e = __expf(lgs[i*65 + j] - m);
        lgs[i*65 + j] = e;
        sum += e;
    }
    float inv = 1.f / sum;
    float acc[28];
    #pragma unroll
    for (int dd = 0; dd < 28; dd++) acc[dd] = 0.f;
    for (int j = 0; j < 64; j++) {
        float a = lgs[i*65 + j] * inv;
        #pragma unroll
        for (int dd = 0; dd < 28; dd++) acc[dd] += a*vs[j*28 + dd];
    }
    size_t ob = (wbase + i)*224 + head*28;
    #pragma unroll
    for (int dd = 0; dd < 28; dd++) obuf[ob + dd] = acc[dd];
}

// ---------------- IWT + crop + final layout ----------------
__global__ void k_iwt(const float* __restrict__ oproj, float* __restrict__ out) {
    size_t id = (size_t)blockIdx.x*256 + threadIdx.x;   // 2293760
    int c = (int)(id % 224); size_t r = id / 224;
    int j = (int)(r % 20); r /= 20;
    int i = (int)(r % 16); int bb = (int)(r / 16);
    int wi = i >> 3, ti = i & 7, wj = j >> 3, tj = j & 7;
    size_t row0 = ((size_t)(bb*6 + wi*3 + wj))*64 + ti*8 + tj;
    float A  = oproj[row0*224 + c];
    float Hh = oproj[(row0 + 12288)*224 + c];
    float V  = oproj[(row0 + 24576)*224 + c];
    float D  = oproj[(row0 + 36864)*224 + c];
    size_t oo = (((size_t)bb*32 + 2*i)*40 + 2*j)*224 + c;
    out[oo]          = 0.5f*(A + Hh + V + D);
    out[oo + 224]    = 0.5f*(A + Hh - V - D);
    out[oo + 8960]   = 0.5f*(A - Hh + V - D);
    out[oo + 9184]   = 0.5f*(A - Hh - V + D);
}

// ---------------- launcher ----------------
extern "C" void kernel_launch(void* const* d_in, const int* in_sizes, int n_in,
                              void* d_out, int out_size) {
    const float* x       = (const float*)d_in[0];
    const float* Wq      = (const float*)d_in[1];
    const float* Wkv     = (const float*)d_in[2];
    const float* ln_g    = (const float*)d_in[3];
    const float* ln_b    = (const float*)d_in[4];
    const float* in_proj = (const float*)d_in[5];
    const float* conv1dW = (const float*)d_in[6];
    const float* conv1db = (const float*)d_in[7];
    const float* x_projW = (const float*)d_in[8];
    const float* dt_projW= (const float*)d_in[9];
    const float* dt_projb= (const float*)d_in[10];
    const float* A_log   = (const float*)d_in[11];
    const float* Dp      = (const float*)d_in[12];
    const float* out_projW=(const float*)d_in[13];
    const float* skip    = (const float*)d_in[14];
    const float* projW   = (const float*)d_in[15];
    const float* projb   = (const float*)d_in[16];
    const float* conv3dW = (const float*)d_in[17];
    const float* conv3db = (const float*)d_in[18];
    const float* Wq1     = (const float*)d_in[19];
    const float* Wkv1    = (const float*)d_in[20];
    const float* pos_emb = (const float*)d_in[21];
    GemmPtrs4 po;
    po.B[0] = (const float*)d_in[22]; po.bias[0] = (const float*)d_in[23];
    po.B[1] = (const float*)d_in[24]; po.bias[1] = (const float*)d_in[25];
    po.B[2] = (const float*)d_in[26]; po.bias[2] = (const float*)d_in[27];
    po.B[3] = (const float*)d_in[28]; po.bias[3] = (const float*)d_in[29];
    float* out = (float*)d_out;

    float *p_q, *p_kv, *p_attn, *p_x1, *p_xn, *p_xz, *p_xc, *p_xdbl, *p_dt,
          *p_Bm, *p_Cm, *p_y, *p_S, *p_sd, *p_H0, *p_xm2, *p_x2, *p_x3,
          *p_xw, *p_qkvw, *p_obuf, *p_oproj;
    cudaGetSymbolAddress((void**)&p_q,    g_q);
    cudaGetSymbolAddress((void**)&p_kv,   g_kv);
    cudaGetSymbolAddress((void**)&p_attn, g_attn);
    cudaGetSymbolAddress((void**)&p_x1,   g_x1);
    cudaGetSymbolAddress((void**)&p_xn,   g_xn);
    cudaGetSymbolAddress((void**)&p_xz,   g_xz);
    cudaGetSymbolAddress((void**)&p_xc,   g_xc);
    cudaGetSymbolAddress((void**)&p_xdbl, g_xdbl);
    cudaGetSymbolAddress((void**)&p_dt,   g_dt);
    cudaGetSymbolAddress((void**)&p_Bm,   g_Bm);
    cudaGetSymbolAddress((void**)&p_Cm,   g_Cm);
    cudaGetSymbolAddress((void**)&p_y,    g_y);
    cudaGetSymbolAddress((void**)&p_S,    g_S);
    cudaGetSymbolAddress((void**)&p_sd,   g_sumdt);
    cudaGetSymbolAddress((void**)&p_H0,   g_H0);
    cudaGetSymbolAddress((void**)&p_xm2,  g_xm2);
    cudaGetSymbolAddress((void**)&p_x2,   g_x2);
    cudaGetSymbolAddress((void**)&p_x3,   g_x3);
    cudaGetSymbolAddress((void**)&p_xw,   g_xw);
    cudaGetSymbolAddress((void**)&p_qkvw, g_qkvw);
    cudaGetSymbolAddress((void**)&p_obuf, g_obuf);
    cudaGetSymbolAddress((void**)&p_oproj,g_oproj);

    // stage 1: q/kv GEMMs, gram+softmax, apply
    sgemm128<<<dim3(2, 320), 256>>>(x, Wq,  p_q,  nullptr, 224, 224, 224, 224, 224);
    sgemm128<<<dim3(4, 320), 256>>>(x, Wkv, p_kv, nullptr, 448, 224, 224, 448, 448);
    k_gram <<<dim3(32, 8), 256>>>(p_q, p_kv, p_attn);
    k_apply<<<dim3(20, 32), 224>>>(x, p_kv, p_attn, p_x1);

    // stage 2: mamba
    k_ln1<<<dim3(40, 32), 256>>>(p_x1, ln_g, ln_b, p_xn);
    sgemm128<<<dim3(1, 2240), 256>>>(p_xn, in_proj, p_xz, nullptr, 128, 32, 32, 128, 128);
    k_conv1d<<<71680, 256>>>(p_xz, conv1dW, conv1db, p_xc);
    sgemm_k<<<dim3(1, 2240), 256>>>(p_xc, x_projW, p_xdbl, nullptr, 34, 64, 64, 34, 34);
    k_dtbc<<<107520, 256>>>(p_xdbl, dt_projW, dt_projb, p_dt, p_Bm, p_Cm);
    k_scan1<<<8960, 256>>>(p_dt, p_xc, p_Bm, A_log, p_S, p_sd);
    k_scan2<<<128, 256>>>(p_S, p_sd, A_log, p_H0);
    k_scan3<<<8960, 256>>>(p_dt, p_xc, p_Bm, p_Cm, A_log, p_H0, p_y);
    k_final<<<35840, 256>>>(p_y, p_xc, p_xz, p_xn, Dp, out_projW, skip,
                            ln_g, ln_b, projW, projb, p_xm2);
    k_addback<<<dim3(40, 32), 256>>>(p_x1, p_xm2, p_x2);

    // stage 3: conv3d
    k_conv3d<<<dim3(40, 32), 224>>>(p_x2, conv3dW, conv3db, p_x3);

    // stage 4: DWT + window attention
    k_dwt<<<43008, 256>>>(p_x3, p_xw);
    sgemm128<<<dim3(2, 384), 256>>>(p_xw, Wq1,  p_qkvw,       nullptr, 224, 224, 224, 224, 672);
    sgemm128<<<dim3(4, 384), 256>>>(p_xw, Wkv1, p_qkvw + 224, nullptr, 448, 224, 224, 448, 672);
    k_wattn<<<dim3(768, 8), 64>>>(p_qkvw, pos_emb, p_obuf);
    // 4 out-proj GEMMs in ONE batched launch (gridDim.z = subband)
    sgemm128_b4<<<dim3(2, 96, 4), 256>>>(p_obuf, po, p_oproj,
                                         224, 224, 224, 224, 224,
                                         (long long)12288*224, (long long)12288*224);

    // stage 5: IWT + output
    k_iwt<<<8960, 256>>>(p_oproj, out);
}

// round 6
// speedup vs baseline: 1.5062x; 1.1307x over previous
#include <cuda_runtime.h>
#include <math.h>
#include <stdint.h>

// ---------------- static scratch (16B aligned) ----------------
__device__ __align__(16) float g_q    [40960u*224u];
__device__ __align__(16) float g_kv   [40960u*448u];
__device__ __align__(16) float g_attn [32*8*28*28];
__device__ __align__(16) float g_x1   [9175040];
__device__ __align__(16) float g_xn   [9175040];      // 286720 x 32
__device__ __align__(16) float g_xz   [36700160];     // 286720 x 128
__device__ __align__(16) float g_xc   [18350080];     // 286720 x 64
__device__ __align__(16) float g_xdbl [9748480];      // 286720 x 34
__device__ __align__(16) float g_dt   [18350080];
__device__ __align__(16) float g_Bm   [4587520];
__device__ __align__(16) float g_Cm   [4587520];
__device__ __align__(16) float g_y    [18350080];
__device__ __align__(16) float g_S    [2293760];      // 32*64*70*16
__device__ __align__(16) float g_sumdt[143360];       // 32*64*70
__device__ __align__(16) float g_H0   [2293760];
__device__ __align__(16) float g_xm2  [9175040];      // 286720 x 32
__device__ __align__(16) float g_x2   [9175040];
__device__ __align__(16) float g_x3   [9175040];
__device__ __align__(16) float g_xw   [11010048];     // 49152 x 224
__device__ __align__(16) float g_qkvw [33030144];     // 49152 x 672
__device__ __align__(16) float g_obuf [11010048];
__device__ __align__(16) float g_oproj[11010048];

__device__ __forceinline__ float siluf(float v){ return v / (1.f + __expf(-v)); }

struct GemmPtrs4 { const float* B[4]; const float* bias[4]; };

// ---------------- SGEMM: 128x64 tile, 8x4 micro, BK=16 (proven config) --------
__device__ __forceinline__ void sgemm_core(
    const float* __restrict__ A, const float* __restrict__ B,
    float* __restrict__ C, const float* __restrict__ bias,
    int N, int K, int lda, int ldb, int ldc,
    float (*As)[128], float (*Bs)[64])
{
    const int bm = blockIdx.y * 128, bn = blockIdx.x * 64;
    const int tid = threadIdx.x;
    const int tr = tid >> 4, tc = tid & 15;
    float acc[8][4];
    #pragma unroll
    for (int i = 0; i < 8; i++)
        #pragma unroll
        for (int j = 0; j < 4; j++) acc[i][j] = 0.f;

    for (int k0 = 0; k0 < K; k0 += 16) {
        #pragma unroll
        for (int i = 0; i < 2; i++) {
            int idx = tid + i * 256;
            int r = idx >> 2, c4 = (idx & 3) * 4;
            float4 v = *(const float4*)(A + (size_t)(bm + r) * lda + k0 + c4);
            As[c4+0][r]=v.x; As[c4+1][r]=v.y; As[c4+2][r]=v.z; As[c4+3][r]=v.w;
        }
        {
            int r = tid >> 4, c0 = (tid & 15) * 4;
            #pragma unroll
            for (int i = 0; i < 4; i++) {
                int n = bn + c0 + i;
                Bs[r][c0+i] = (n < N) ? B[(size_t)(k0 + r) * ldb + n] : 0.f;
            }
        }
        __syncthreads();
        #pragma unroll
        for (int kk = 0; kk < 16; kk++) {
            float4 a0 = *(const float4*)&As[kk][tr*8];
            float4 a1 = *(const float4*)&As[kk][tr*8+4];
            float4 b0 = *(const float4*)&Bs[kk][tc*4];
            float a[8] = {a0.x,a0.y,a0.z,a0.w,a1.x,a1.y,a1.z,a1.w};
            float b[4] = {b0.x,b0.y,b0.z,b0.w};
            #pragma unroll
            for (int i = 0; i < 8; i++)
                #pragma unroll
                for (int j = 0; j < 4; j++) acc[i][j] += a[i]*b[j];
        }
        __syncthreads();
    }
    #pragma unroll
    for (int i = 0; i < 8; i++) {
        int m = bm + tr*8 + i;
        #pragma unroll
        for (int j = 0; j < 4; j++) {
            int n = bn + tc*4 + j;
            if (n < N) {
                float v = acc[i][j];
                if (bias) v += bias[n];
                C[(size_t)m * ldc + n] = v;
            }
        }
    }
}

__global__ void sgemm_k(const float* __restrict__ A, const float* __restrict__ B,
                        float* __restrict__ C, const float* __restrict__ bias,
                        int N, int K, int lda, int ldb, int ldc) {
    __shared__ float As[16][128];
    __shared__ float Bs[16][64];
    sgemm_core(A, B, C, bias, N, K, lda, ldb, ldc, As, Bs);
}

// batched variant: per-z B/bias, A and C strided by z
__global__ void sgemm_b4(const float* __restrict__ A, GemmPtrs4 p,
                         float* __restrict__ C,
                         int N, int K, int lda, int ldb, int ldc,
                         long long strideA, long long strideC) {
    __shared__ float As[16][128];
    __shared__ float Bs[16][64];
    int z = blockIdx.z;
    sgemm_core(A + (size_t)z * strideA, p.B[z], C + (size_t)z * strideC,
               p.bias[z], N, K, lda, ldb, ldc, As, Bs);
}

// ---------------- stage 1: channel attention ----------------
__global__ void k_gram(const float* __restrict__ q, const float* __restrict__ kv,
                       float* __restrict__ attn) {
    int b = blockIdx.x, h = blockIdx.y;
    __shared__ float kt[32][28], qt[32][28];
    __shared__ float G[840];
    int tid = threadIdx.x;   // 256
    float acc[4] = {0.f,0.f,0.f,0.f};
    for (int nt = 0; nt < 40; nt++) {
        for (int idx = tid; idx < 896; idx += 256) {
            int n = idx / 28, i = idx % 28;
            size_t row = (size_t)b*1280 + nt*32 + n;
            kt[n][i] = kv[row*448 + h*28 + i];
            qt[n][i] = q [row*224 + h*28 + i];
        }
        __syncthreads();
        #pragma unroll
        for (int s = 0; s < 4; s++) {
            int w = tid + 256*s;
            if (w < 784) {
                int i = w/28, j = w%28; float a = acc[s];
                #pragma unroll
                for (int n = 0; n < 32; n++) a += kt[n][i]*qt[n][j];
                acc[s] = a;
            } else if (w < 812) {
                int i = w - 784; float a = acc[s];
                #pragma unroll
                for (int n = 0; n < 32; n++) a += kt[n][i]*kt[n][i];
                acc[s] = a;
            } else if (w < 840) {
                int j = w - 812; float a = acc[s];
                #pragma unroll
                for (int n = 0; n < 32; n++) a += qt[n][j]*qt[n][j];
                acc[s] = a;
            }
        }
        __syncthreads();
    }
    #pragma unroll
    for (int s = 0; s < 4; s++) { int w = tid + 256*s; if (w < 840) G[w] = acc[s]; }
    __syncthreads();
    if (tid < 28) {
        int i = tid;
        float nk = fmaxf(sqrtf(G[784+i]), 1e-12f);
        float lg[28], m = -1e30f;
        #pragma unroll
        for (int j = 0; j < 28; j++) {
            float nq = fmaxf(sqrtf(G[812+j]), 1e-12f);
            lg[j] = G[i*28+j] / (nk*nq) * 0.18898223650461363f;
            m = fmaxf(m, lg[j]);
        }
        float sum = 0.f;
        #pragma unroll
        for (int j = 0; j < 28; j++) { lg[j] = __expf(lg[j]-m); sum += lg[j]; }
        float inv = 1.f/sum;
        #pragma unroll
        for (int j = 0; j < 28; j++)
            attn[(((size_t)b*8 + h)*28 + i)*28 + j] = lg[j]*inv;
    }
}

// x1 = attn-applied + residual; 8 rows per barrier interval
__global__ void k_apply(const float* __restrict__ x, const float* __restrict__ kv,
                        const float* __restrict__ attn, float* __restrict__ x1) {
    int chunk = blockIdx.x, b = blockIdx.y;
    __shared__ float att[6272];
    __shared__ float vr[8][224];
    int tid = threadIdx.x;   // 224
    for (int idx = tid; idx < 6272; idx += 224) att[idx] = attn[(size_t)b*6272 + idx];
    int h = tid / 28, i = tid % 28;
    for (int nn = 0; nn < 64; nn += 8) {
        size_t row0 = (size_t)b*1280 + chunk*64 + nn;
        __syncthreads();
        for (int idx = tid; idx < 1792; idx += 224) {
            int rr = idx / 224, cc = idx % 224;
            vr[rr][cc] = kv[(row0 + rr)*448 + 224 + cc];
        }
        __syncthreads();
        #pragma unroll
        for (int rr = 0; rr < 8; rr++) {
            float a = 0.f;
            #pragma unroll
            for (int j = 0; j < 28; j++) a += att[(h*28+i)*28 + j] * vr[rr][h*28 + j];
            size_t o = (row0 + rr)*224 + tid;
            x1[o] = x[o] + a;
        }
    }
}

// ---------------- transpose + LN into (b, L=8960, 32) ----------------
__global__ void k_ln1(const float* __restrict__ x1, const float* __restrict__ g,
                      const float* __restrict__ be, float* __restrict__ xn) {
    int ww = blockIdx.x, b = blockIdx.y;
    __shared__ float s[32*225];
    int tid = threadIdx.x;   // 256
    for (int idx = tid; idx < 32*224; idx += 256) {
        int m = idx / 224, cc = idx % 224;
        s[m*225 + cc] = x1[((size_t)b*1280 + m*40 + ww)*224 + cc];
    }
    __syncthreads();
    for (int cc = tid; cc < 224; cc += 256) {
        float mean = 0.f;
        #pragma unroll
        for (int m = 0; m < 32; m++) mean += s[m*225+cc];
        mean *= (1.f/32.f);
        float var = 0.f;
        #pragma unroll
        for (int m = 0; m < 32; m++) { float d = s[m*225+cc]-mean; var += d*d; }
        var *= (1.f/32.f);
        float inv = rsqrtf(var + 1e-5f);
        size_t ob = ((size_t)b*8960 + ww*224 + cc)*32;
        #pragma unroll
        for (int m = 0; m < 32; m++)
            xn[ob + m] = (s[m*225+cc]-mean)*inv*g[m] + be[m];
    }
}

// ---------------- mamba pieces ----------------
__global__ void k_conv1d(const float* __restrict__ xz, const float* __restrict__ cw,
                         const float* __restrict__ cb, float* __restrict__ xc) {
    size_t id = (size_t)blockIdx.x*256 + threadIdx.x;
    size_t row = id >> 6; int d = (int)(id & 63);
    size_t b = row / 8960; int l = (int)(row % 8960);
    float acc = cb[d];
    #pragma unroll
    for (int t = 0; t < 4; t++) {
        int ls = l - 3 + t;
        if (ls >= 0) acc += xz[((size_t)b*8960 + ls)*128 + d] * cw[d*4 + t];
    }
    xc[row*64 + d] = siluf(acc);
}

__global__ void k_dtbc(const float* __restrict__ xdbl, const float* __restrict__ dtW,
                       const float* __restrict__ dtb, float* __restrict__ dt,
                       float* __restrict__ Bm, float* __restrict__ Cm) {
    size_t id = (size_t)blockIdx.x*256 + threadIdx.x;
    size_t row = id / 96; int j = (int)(id % 96);
    const float* xd = xdbl + row*34;
    if (j < 64) {
        float v = xd[0]*dtW[j] + xd[1]*dtW[64+j] + dtb[j];
        dt[row*64 + j] = (v > 20.f) ? v : log1pf(__expf(v));
    } else if (j < 80) {
        Bm[row*16 + (j-64)] = xd[2 + (j-64)];
    } else {
        Cm[row*16 + (j-80)] = xd[18 + (j-80)];
    }
}

__global__ void k_scan1(const float* __restrict__ dt, const float* __restrict__ xc,
                        const float* __restrict__ Bm, const float* __restrict__ Alog,
                        float* __restrict__ S, float* __restrict__ sumdt) {
    int gw = (blockIdx.x*256 + threadIdx.x) >> 5;
    int lane = threadIdx.x & 31;
    int b = gw / 2240; int rem = gw % 2240;
    int chunk = rem >> 5; int dp = rem & 31;
    int d = dp*2 + (lane >> 4); int n = lane & 15;
    float Av = -__expf(Alog[d*16 + n]);
    float h = 0.f, sdt = 0.f;
    size_t base = (size_t)b*8960 + chunk*128;
    #pragma unroll 4
    for (int l = 0; l < 128; l++) {
        size_t row = base + l;
        float dtv = dt[row*64 + d];
        float u   = xc[row*64 + d];
        float Bn  = Bm[row*16 + n];
        h = __expf(Av*dtv)*h + dtv*u*Bn;
        sdt += dtv;
    }
    size_t idx = (size_t)(b*64 + d)*70 + chunk;
    S[idx*16 + n] = h;
    if (n == 0) sumdt[idx] = sdt;
}

__global__ void k_scan2(const float* __restrict__ S, const float* __restrict__ sumdt,
                        const float* __restrict__ Alog, float* __restrict__ H0) {
    int t = blockIdx.x*256 + threadIdx.x;
    int b = t >> 10; int d = (t >> 4) & 63; int n = t & 15;
    float Av = -__expf(Alog[d*16 + n]);
    float carry = 0.f;
    size_t base = (size_t)(b*64 + d)*70;
    for (int ch = 0; ch < 70; ch++) {
        size_t idx = base + ch;
        H0[idx*16 + n] = carry;
        carry = carry*__expf(Av*sumdt[idx]) + S[idx*16 + n];
    }
}

__global__ void k_scan3(const float* __restrict__ dt, const float* __restrict__ xc,
                        const float* __restrict__ Bm, const float* __restrict__ Cm,
                        const float* __restrict__ Alog, const float* __restrict__ H0,
                        float* __restrict__ y) {
    int gw = (blockIdx.x*256 + threadIdx.x) >> 5;
    int lane = threadIdx.x & 31;
    int b = gw / 2240; int rem = gw % 2240;
    int chunk = rem >> 5; int dp = rem & 31;
    int d = dp*2 + (lane >> 4); int n = lane & 15;
    float Av = -__expf(Alog[d*16 + n]);
    size_t idx = (size_t)(b*64 + d)*70 + chunk;
    float h = H0[idx*16 + n];
    size_t base = (size_t)b*8960 + chunk*128;
    #pragma unroll 4
    for (int l = 0; l < 128; l++) {
        size_t row = base + l;
        float dtv = dt[row*64 + d];
        float u   = xc[row*64 + d];
        float Bn  = Bm[row*16 + n];
        h = __expf(Av*dtv)*h + dtv*u*Bn;
        float yv = h * Cm[row*16 + n];
        yv += __shfl_xor_sync(0xffffffffu, yv, 8);
        yv += __shfl_xor_sync(0xffffffffu, yv, 4);
        yv += __shfl_xor_sync(0xffffffffu, yv, 2);
        yv += __shfl_xor_sync(0xffffffffu, yv, 1);
        if (n == 0) y[row*64 + d] = yv;
    }
}

// gate + out_proj + skip + LN + proj; each warp handles 8 rows
__global__ void k_final(const float* __restrict__ y, const float* __restrict__ xc,
                        const float* __restrict__ xz, const float* __restrict__ xn,
                        const float* __restrict__ Dp, const float* __restrict__ opW,
                        const float* __restrict__ skipp, const float* __restrict__ g,
                        const float* __restrict__ be, const float* __restrict__ projW,
                        const float* __restrict__ projb, float* __restrict__ xm2) {
    __shared__ float sop[2048], spj[1024];
    int tid = threadIdx.x;   // 256
    for (int i = tid; i < 2048; i += 256) sop[i] = opW[i];
    for (int i = tid; i < 1024; i += 256) spj[i] = projW[i];
    __syncthreads();
    int warp = tid >> 5, lane = tid & 31;
    float skip = skipp[0];
    float dpl = Dp[lane], dph = Dp[32+lane];
    float gl = g[lane], bel = be[lane], pbl = projb[lane];
    #pragma unroll
    for (int t = 0; t < 8; t++) {
        size_t r = ((size_t)blockIdx.x*8 + warp)*8 + t;
        float y0 = y[r*64 + lane],      y1 = y[r*64 + 32 + lane];
        float c0 = xc[r*64 + lane],     c1 = xc[r*64 + 32 + lane];
        float z0 = xz[r*128 + 64 + lane], z1 = xz[r*128 + 96 + lane];
        float yy0 = (y0 + c0*dpl) * siluf(z0);
        float yy1 = (y1 + c1*dph) * siluf(z1);
        float acc = 0.f;
        #pragma unroll
        for (int d = 0; d < 32; d++) acc += __shfl_sync(0xffffffffu, yy0, d) * sop[d*32 + lane];
        #pragma unroll
        for (int d = 0; d < 32; d++) acc += __shfl_sync(0xffffffffu, yy1, d) * sop[(d+32)*32 + lane];
        float xm = acc + skip * xn[r*32 + lane];
        float mean = xm;
        #pragma unroll
        for (int o = 16; o; o >>= 1) mean += __shfl_xor_sync(0xffffffffu, mean, o);
        mean *= (1.f/32.f);
        float dv = xm - mean, var = dv*dv;
        #pragma unroll
        for (int o = 16; o; o >>= 1) var += __shfl_xor_sync(0xffffffffu, var, o);
        var *= (1.f/32.f);
        float v = dv * rsqrtf(var + 1e-5f) * gl + bel;
        float acc2 = pbl;
        #pragma unroll
        for (int mm = 0; mm < 32; mm++) acc2 += __shfl_sync(0xffffffffu, v, mm) * spj[mm*32 + lane];
        xm2[r*32 + lane] = acc2;
    }
}

__global__ void k_addback(const float* __restrict__ x1, const float* __restrict__ xm2,
                          float* __restrict__ x2) {
    int ww = blockIdx.x, b = blockIdx.y;
    __shared__ float s[224*33];
    int tid = threadIdx.x;   // 256
    for (int idx = tid; idx < 224*32; idx += 256) {
        int cc = idx >> 5, m = idx & 31;
        s[cc*33 + m] = xm2[((size_t)b*8960 + ww*224 + cc)*32 + m];
    }
    __syncthreads();
    for (int idx = tid; idx < 32*224; idx += 256) {
        int m = idx / 224, cc = idx % 224;
        size_t o = ((size_t)b*1280 + m*40 + ww)*224 + cc;
        x2[o] = x1[o] + s[cc*33 + m];
    }
}

// ---------------- conv3d 5x5x5, pad 2, smem-tiled per ky-plane ----------------
__global__ void k_conv3d(const float* __restrict__ x2, const float* __restrict__ cw,
                         const float* __restrict__ cb, float* __restrict__ x3) {
    int y = blockIdx.x, b = blockIdx.y;
    int xx = threadIdx.x;   // 224
    __shared__ float ws[125];
    __shared__ float sp[32][228];   // one ky plane: 32 i-planes x (224 + halo)
    if (xx < 125) ws[xx] = cw[xx];
    if (xx < 32) { sp[xx][0]=0.f; sp[xx][1]=0.f; sp[xx][226]=0.f; sp[xx][227]=0.f; }
    float acc[32];
    #pragma unroll
    for (int d = 0; d < 32; d++) acc[d] = 0.f;
    for (int ky = 0; ky < 5; ky++) {
        int yy = y + ky - 2;
        if (yy < 0 || yy >= 40) continue;
        __syncthreads();
        for (int i = 0; i < 32; i++)
            sp[i][xx+2] = x2[(((size_t)b*32 + i)*40 + yy)*224 + xx];
        __syncthreads();
        #pragma unroll
        for (int kx = 0; kx < 5; kx++) {
            float v[36];
            v[0]=v[1]=v[34]=v[35]=0.f;
            #pragma unroll
            for (int i = 0; i < 32; i++) v[i+2] = sp[i][xx + kx];
            #pragma unroll
            for (int kz = 0; kz < 5; kz++) {
                float wv = ws[(kz*5 + ky)*5 + kx];
                #pragma unroll
                for (int d = 0; d < 32; d++) acc[d] += v[d+kz]*wv;
            }
        }
    }
    float bias = cb[0];
    #pragma unroll
    for (int d = 0; d < 32; d++)
        x3[(((size_t)b*32 + d)*40 + y)*224 + xx] = acc[d] + bias;
}

// ---------------- DWT + reflect-pad + window pack ----------------
__global__ void k_dwt(const float* __restrict__ x3, float* __restrict__ xw) {
    size_t id = (size_t)blockIdx.x*256 + threadIdx.x;   // 11010048
    int c = (int)(id % 224); size_t r = id / 224;
    int sub = (int)(r / 12288); int rw = (int)(r % 12288);
    int win = rw >> 6, tok = rw & 63;
    int bb = win / 6, w6 = win % 6;
    int wi = w6 / 3, wj = w6 % 3;
    int ti = tok >> 3, tj = tok & 7;
    int i2 = wi*8 + ti;
    int j2 = wj*8 + tj;
    int j = (j2 < 20) ? j2 : 38 - j2;   // reflect pad
    size_t base = (((size_t)bb*32 + 2*i2)*40 + 2*j)*224 + c;
    float a  = x3[base],        bv = x3[base + 224];
    float c2 = x3[base + 8960], d2 = x3[base + 9184];
    float val;
    if      (sub == 0) val = a + bv + c2 + d2;
    else if (sub == 1) val = a + bv - c2 - d2;
    else if (sub == 2) val = a - bv + c2 - d2;
    else               val = a - bv - c2 + d2;
    xw[id] = 0.5f * val;
}

// ---------------- window attention (float4 smem reads) ----------------
__global__ void k_wattn(const float* __restrict__ qkvw, const float* __restrict__ pe,
                        float* __restrict__ obuf) {
    int win = blockIdx.x, head = blockIdx.y;
    __shared__ __align__(16) float qs[64*28], ks[64*28], vs[64*28];
    __shared__ float lgs[64*65];
    int tid = threadIdx.x;   // 64
    size_t wbase = (size_t)win * 64;
    for (int idx = tid; idx < 1792; idx += 64) {
        int tok = idx / 28, dd = idx % 28;
        size_t rb = (wbase + tok)*672 + head*28 + dd;
        qs[idx] = qkvw[rb] * 0.18898223650461363f;
        ks[idx] = qkvw[rb + 224];
        vs[idx] = qkvw[rb + 448];
    }
    __syncthreads();
    int i = tid;
    float qr[28];
    #pragma unroll
    for (int dd = 0; dd < 28; dd++) qr[dd] = qs[i*28 + dd];
    const float* per = pe + ((size_t)head*64 + i)*64;
    float m = -1e30f;
    for (int j = 0; j < 64; j++) {
        const float4* k4 = (const float4*)&ks[j*28];   // 28*4B = 112B, 16B-aligned
        float dot = 0.f;
        #pragma unroll
        for (int q4 = 0; q4 < 7; q4++) {
            float4 kk = k4[q4];
            dot += qr[q4*4+0]*kk.x + qr[q4*4+1]*kk.y
                 + qr[q4*4+2]*kk.z + qr[q4*4+3]*kk.w;
        }
        float l = dot + per[j];
        lgs[i*65 + j] = l;
        m = fmaxf(m, l);
    }
    float sum = 0.f;
    for (int j = 0; j < 64; j++) {
        float e = __expf(lgs[i*65 + j] - m);
        lgs[i*65 + j] = e;
        sum += e;
    }
    float inv = 1.f / sum;
    float acc[28];
    #pragma unroll
    for (int dd = 0; dd < 28; dd++) acc[dd] = 0.f;
    for (int j = 0; j < 64; j++) {
        float a = lgs[i*65 + j] * inv;
        const float4* v4 = (const float4*)&vs[j*28];
        #pragma unroll
        for (int q4 = 0; q4 < 7; q4++) {
            float4 vv = v4[q4];
            acc[q4*4+0] += a*vv.x; acc[q4*4+1] += a*vv.y;
            acc[q4*4+2] += a*vv.z; acc[q4*4+3] += a*vv.w;
        }
    }
    size_t ob = (wbase + i)*224 + head*28;
    #pragma unroll
    for (int dd = 0; dd < 28; dd++) obuf[ob + dd] = acc[dd];
}

// ---------------- IWT + crop + final layout ----------------
__global__ void k_iwt(const float* __restrict__ oproj, float* __restrict__ out) {
    size_t id = (size_t)blockIdx.x*256 + threadIdx.x;   // 2293760
    int c = (int)(id % 224); size_t r = id / 224;
    int j = (int)(r % 20); r /= 20;
    int i = (int)(r % 16); int bb = (int)(r / 16);
    int wi = i >> 3, ti = i & 7, wj = j >> 3, tj = j & 7;
    size_t row0 = ((size_t)(bb*6 + wi*3 + wj))*64 + ti*8 + tj;
    float A  = oproj[row0*224 + c];
    float Hh = oproj[(row0 + 12288)*224 + c];
    float V  = oproj[(row0 + 24576)*224 + c];
    float D  = oproj[(row0 + 36864)*224 + c];
    size_t oo = (((size_t)bb*32 + 2*i)*40 + 2*j)*224 + c;
    out[oo]          = 0.5f*(A + Hh + V + D);
    out[oo + 224]    = 0.5f*(A + Hh - V - D);
    out[oo + 8960]   = 0.5f*(A - Hh + V - D);
    out[oo + 9184]   = 0.5f*(A - Hh - V + D);
}

// ---------------- launcher ----------------
extern "C" void kernel_launch(void* const* d_in, const int* in_sizes, int n_in,
                              void* d_out, int out_size) {
    const float* x       = (const float*)d_in[0];
    const float* Wq      = (const float*)d_in[1];
    const float* Wkv     = (const float*)d_in[2];
    const float* ln_g    = (const float*)d_in[3];
    const float* ln_b    = (const float*)d_in[4];
    const float* in_proj = (const float*)d_in[5];
    const float* conv1dW = (const float*)d_in[6];
    const float* conv1db = (const float*)d_in[7];
    const float* x_projW = (const float*)d_in[8];
    const float* dt_projW= (const float*)d_in[9];
    const float* dt_projb= (const float*)d_in[10];
    const float* A_log   = (const float*)d_in[11];
    const float* Dp      = (const float*)d_in[12];
    const float* out_projW=(const float*)d_in[13];
    const float* skip    = (const float*)d_in[14];
    const float* projW   = (const float*)d_in[15];
    const float* projb   = (const float*)d_in[16];
    const float* conv3dW = (const float*)d_in[17];
    const float* conv3db = (const float*)d_in[18];
    const float* Wq1     = (const float*)d_in[19];
    const float* Wkv1    = (const float*)d_in[20];
    const float* pos_emb = (const float*)d_in[21];
    GemmPtrs4 po;
    po.B[0] = (const float*)d_in[22]; po.bias[0] = (const float*)d_in[23];
    po.B[1] = (const float*)d_in[24]; po.bias[1] = (const float*)d_in[25];
    po.B[2] = (const float*)d_in[26]; po.bias[2] = (const float*)d_in[27];
    po.B[3] = (const float*)d_in[28]; po.bias[3] = (const float*)d_in[29];
    float* out = (float*)d_out;

    float *p_q, *p_kv, *p_attn, *p_x1, *p_xn, *p_xz, *p_xc, *p_xdbl, *p_dt,
          *p_Bm, *p_Cm, *p_y, *p_S, *p_sd, *p_H0, *p_xm2, *p_x2, *p_x3,
          *p_xw, *p_qkvw, *p_obuf, *p_oproj;
    cudaGetSymbolAddress((void**)&p_q,    g_q);
    cudaGetSymbolAddress((void**)&p_kv,   g_kv);
    cudaGetSymbolAddress((void**)&p_attn, g_attn);
    cudaGetSymbolAddress((void**)&p_x1,   g_x1);
    cudaGetSymbolAddress((void**)&p_xn,   g_xn);
    cudaGetSymbolAddress((void**)&p_xz,   g_xz);
    cudaGetSymbolAddress((void**)&p_xc,   g_xc);
    cudaGetSymbolAddress((void**)&p_xdbl, g_xdbl);
    cudaGetSymbolAddress((void**)&p_dt,   g_dt);
    cudaGetSymbolAddress((void**)&p_Bm,   g_Bm);
    cudaGetSymbolAddress((void**)&p_Cm,   g_Cm);
    cudaGetSymbolAddress((void**)&p_y,    g_y);
    cudaGetSymbolAddress((void**)&p_S,    g_S);
    cudaGetSymbolAddress((void**)&p_sd,   g_sumdt);
    cudaGetSymbolAddress((void**)&p_H0,   g_H0);
    cudaGetSymbolAddress((void**)&p_xm2,  g_xm2);
    cudaGetSymbolAddress((void**)&p_x2,   g_x2);
    cudaGetSymbolAddress((void**)&p_x3,   g_x3);
    cudaGetSymbolAddress((void**)&p_xw,   g_xw);
    cudaGetSymbolAddress((void**)&p_qkvw, g_qkvw);
    cudaGetSymbolAddress((void**)&p_obuf, g_obuf);
    cudaGetSymbolAddress((void**)&p_oproj,g_oproj);

    // stage 1: q/kv GEMMs, gram+softmax, apply
    sgemm_k<<<dim3(4, 320), 256>>>(x, Wq,  p_q,  nullptr, 224, 224, 224, 224, 224);
    sgemm_k<<<dim3(7, 320), 256>>>(x, Wkv, p_kv, nullptr, 448, 224, 224, 448, 448);
    k_gram <<<dim3(32, 8), 256>>>(p_q, p_kv, p_attn);
    k_apply<<<dim3(20, 32), 224>>>(x, p_kv, p_attn, p_x1);

    // stage 2: mamba
    k_ln1<<<dim3(40, 32), 256>>>(p_x1, ln_g, ln_b, p_xn);
    sgemm_k<<<dim3(2, 2240), 256>>>(p_xn, in_proj, p_xz, nullptr, 128, 32, 32, 128, 128);
    k_conv1d<<<71680, 256>>>(p_xz, conv1dW, conv1db, p_xc);
    sgemm_k<<<dim3(1, 2240), 256>>>(p_xc, x_projW, p_xdbl, nullptr, 34, 64, 64, 34, 34);
    k_dtbc<<<107520, 256>>>(p_xdbl, dt_projW, dt_projb, p_dt, p_Bm, p_Cm);
    k_scan1<<<8960, 256>>>(p_dt, p_xc, p_Bm, A_log, p_S, p_sd);
    k_scan2<<<128, 256>>>(p_S, p_sd, A_log, p_H0);
    k_scan3<<<8960, 256>>>(p_dt, p_xc, p_Bm, p_Cm, A_log, p_H0, p_y);
    k_final<<<4480, 256>>>(p_y, p_xc, p_xz, p_xn, Dp, out_projW, skip,
                           ln_g, ln_b, projW, projb, p_xm2);
    k_addback<<<dim3(40, 32), 256>>>(p_x1, p_xm2, p_x2);

    // stage 3: conv3d
    k_conv3d<<<dim3(40, 32), 224>>>(p_x2, conv3dW, conv3db, p_x3);

    // stage 4: DWT + window attention
    k_dwt<<<43008, 256>>>(p_x3, p_xw);
    sgemm_k<<<dim3(4, 384), 256>>>(p_xw, Wq1,  p_qkvw,       nullptr, 224, 224, 224, 224, 672);
    sgemm_k<<<dim3(7, 384), 256>>>(p_xw, Wkv1, p_qkvw + 224, nullptr, 448, 224, 224, 448, 672);
    k_wattn<<<dim3(768, 8), 64>>>(p_qkvw, pos_emb, p_obuf);
    // 4 out-proj GEMMs in ONE batched launch (gridDim.z = subband)
    sgemm_b4<<<dim3(4, 96, 4), 256>>>(p_obuf, po, p_oproj,
                                      224, 224, 224, 224, 224,
                                      (long long)12288*224, (long long)12288*224);

    // stage 5: IWT + output
    k_iwt<<<8960, 256>>>(p_oproj, out);
}